// round 11
// baseline (speedup 1.0000x reference)
#include <cuda_runtime.h>
#include <math.h>
#include <stdint.h>

// Problem constants
#define BT  16384   // B*T
#define TT  2048    // T
#define CC  1024    // C
#define HH  16      // heads
#define DD  64      // head dim
#define DLOW 64

// ---------------------------------------------------------------------------
// Scratch (aliased lifetimes, ~322 MB)
// ---------------------------------------------------------------------------
#define S_BIG   ((size_t)BT * CC)
#define OFF_R    ((size_t)0)
#define OFF_K    ((size_t)1 * S_BIG)         // aliases KK
#define OFF_V    ((size_t)2 * S_BIG)
#define OFF_GATE ((size_t)3 * S_BIG)         // aliases XNG
#define OFF_KV   ((size_t)4 * S_BIG)         // aliases WKV
#define OFF_HW   ((size_t)5 * S_BIG)
#define OFF_HA   (OFF_HW + (size_t)BT * 64)
#define OFF_HG   (OFF_HA + (size_t)BT * 64)
#define OFF_WD   (OFF_HG + (size_t)BT * 64)
#define OFF_AB   (OFF_WD + (size_t)BT * HH)
#define SCR_TOTAL (OFF_AB + (size_t)BT * HH)

__device__ float g_scr[SCR_TOTAL];

// ---------------------------------------------------------------------------
// Helpers
// ---------------------------------------------------------------------------
#define EPI_NONE 0
#define EPI_TANH 1
#define EPI_SIG  2

template <int EPI>
__device__ __forceinline__ float epi_apply(float x) {
    if (EPI == EPI_TANH) return tanhf(x);
    if (EPI == EPI_SIG)  return 1.0f / (1.0f + expf(-x));
    return x;
}

__device__ __forceinline__ float to_tf32(float x) {
    uint32_t o;
    asm("cvt.rna.tf32.f32 %0, %1;" : "=r"(o) : "f"(x));
    return __uint_as_float(o);
}

__device__ __forceinline__ void mma_tf32(float* c, const uint32_t* a,
                                         uint32_t b0, uint32_t b1) {
    asm("mma.sync.aligned.m16n8k8.row.col.f32.tf32.tf32.f32 "
        "{%0,%1,%2,%3}, {%4,%5,%6,%7}, {%8,%9}, {%0,%1,%2,%3};"
        : "+f"(c[0]), "+f"(c[1]), "+f"(c[2]), "+f"(c[3])
        : "r"(a[0]), "r"(a[1]), "r"(a[2]), "r"(a[3]), "r"(b0), "r"(b1));
}

// token-shift mix: a = x + (x - x_prev) * coef  (prev = 0 at t == 0)
template <bool MIX>
__device__ __forceinline__ float4 load_a_frag(const float* __restrict__ A,
                                              const float* __restrict__ coef,
                                              int m, int K, int kidx) {
    float4 cur = *(const float4*)(A + (size_t)m * K + kidx);
    if (MIX) {
        float4 pr = make_float4(0.f, 0.f, 0.f, 0.f);
        if ((m & (TT - 1)) != 0)
            pr = *(const float4*)(A + (size_t)(m - 1) * K + kidx);
        float4 cf = *(const float4*)(coef + kidx);
        cur.x = fmaf(cur.x - pr.x, cf.x, cur.x);
        cur.y = fmaf(cur.y - pr.y, cf.y, cur.y);
        cur.z = fmaf(cur.z - pr.z, cf.z, cur.z);
        cur.w = fmaf(cur.w - pr.w, cf.w, cur.w);
    }
    return cur;
}

// ---------------------------------------------------------------------------
// TF32 mma.sync GEMM: C[M,N] = epi(mix(A)[M,K] @ B[K,N]).
// BM=128, BK=32, 256 threads (8 warps). BN in {128, 64}.
// Register-staged double-buffered smem, 1 barrier per K-tile.
// Inner loop: explicit fragment double-buffering (LDS for k-step s+1 issued
// before the HMMAs of step s) to keep the tensor pipe fed at 2 warps/SMSP.
//   As[buf][m][k]  stride 36 ; Bs[buf][k][n] stride BN+8
// ---------------------------------------------------------------------------
template <int BN, int EPI, bool MIX>
__device__ __forceinline__ void
mma_gemm_body(const float* __restrict__ A, const float* __restrict__ coef,
              const float* __restrict__ B, float* __restrict__ C,
              int M, int N, int K) {
    constexpr int BM = 128, BK = 32;
    constexpr int WARPS_N = (BN == 128) ? 4 : 2;
    constexpr int WM = BM / (8 / WARPS_N);
    constexpr int WN = BN / WARPS_N;
    constexpr int MT = WM / 16;
    constexpr int NT = WN / 8;
    constexpr int KS = BK / 8;
    constexpr int ASTR = BK + 4;
    constexpr int BSTR = BN + 8;
    constexpr int BCOL4 = BN / 4;
    constexpr int BKR = 256 / BCOL4;
    constexpr int BQ = BK / BKR;

    extern __shared__ float sm[];
    float* AsBase = sm;
    float* BsBase = sm + 2 * BM * ASTR;

    const int tid = threadIdx.x;
    const int bm = blockIdx.y, bn = blockIdx.x;
    const int wid = tid >> 5, lane = tid & 31;
    const int lr = lane >> 2, lc = lane & 3;
    const int wM = wid / WARPS_N, wN = wid % WARPS_N;

    const int am = tid >> 1;
    const int ak0 = (tid & 1) * 16;
    const int gm = bm * BM + am;
    const int bkr = tid / BCOL4;
    const int bnc = (tid % BCOL4) * 4;

    float acc[MT][NT][4];
#pragma unroll
    for (int i = 0; i < MT; i++)
#pragma unroll
        for (int j = 0; j < NT; j++)
#pragma unroll
            for (int q = 0; q < 4; q++) acc[i][j][q] = 0.f;

    const int nk = K / BK;
    float4 aR[4];
    float4 bR[BQ];

#pragma unroll
    for (int q = 0; q < 4; q++)
        aR[q] = load_a_frag<MIX>(A, coef, gm, K, ak0 + q * 4);
#pragma unroll
    for (int q = 0; q < BQ; q++)
        bR[q] = *(const float4*)(B + (size_t)(bkr + q * BKR) * N + bn * BN + bnc);

    {
#pragma unroll
        for (int q = 0; q < 4; q++) {
            float4 t4 = aR[q];
            t4.x = to_tf32(t4.x); t4.y = to_tf32(t4.y);
            t4.z = to_tf32(t4.z); t4.w = to_tf32(t4.w);
            *(float4*)(AsBase + am * ASTR + ak0 + q * 4) = t4;
        }
#pragma unroll
        for (int q = 0; q < BQ; q++) {
            float4 t4 = bR[q];
            t4.x = to_tf32(t4.x); t4.y = to_tf32(t4.y);
            t4.z = to_tf32(t4.z); t4.w = to_tf32(t4.w);
            *(float4*)(BsBase + (bkr + q * BKR) * BSTR + bnc) = t4;
        }
    }
    __syncthreads();

    int cur = 0;
    for (int kt = 0; kt < nk; kt++) {
        if (kt + 1 < nk) {
            const int kb = (kt + 1) * BK;
#pragma unroll
            for (int q = 0; q < 4; q++)
                aR[q] = load_a_frag<MIX>(A, coef, gm, K, kb + ak0 + q * 4);
#pragma unroll
            for (int q = 0; q < BQ; q++)
                bR[q] = *(const float4*)(B + (size_t)(kb + bkr + q * BKR) * N + bn * BN + bnc);
        }

        const float* Asb = AsBase + cur * BM * ASTR;
        const float* Bsb = BsBase + cur * BK * BSTR;

        // ---- fragment double-buffered MMA loop ----
        uint32_t afP[2][MT][4];
        uint32_t bfP[2][NT][2];
#pragma unroll
        for (int mt = 0; mt < MT; mt++) {
            const float* ap = Asb + (wM * WM + mt * 16 + lr) * ASTR + lc;
            afP[0][mt][0] = __float_as_uint(ap[0]);
            afP[0][mt][1] = __float_as_uint(ap[8 * ASTR]);
            afP[0][mt][2] = __float_as_uint(ap[4]);
            afP[0][mt][3] = __float_as_uint(ap[8 * ASTR + 4]);
        }
#pragma unroll
        for (int nt = 0; nt < NT; nt++) {
            const float* bp = Bsb + lc * BSTR + wN * WN + nt * 8 + lr;
            bfP[0][nt][0] = __float_as_uint(bp[0]);
            bfP[0][nt][1] = __float_as_uint(bp[4 * BSTR]);
        }
#pragma unroll
        for (int ks = 0; ks < KS; ks++) {
            const int cb = ks & 1;
            const int nb = cb ^ 1;
            if (ks + 1 < KS) {
                const int k0 = (ks + 1) * 8;
#pragma unroll
                for (int mt = 0; mt < MT; mt++) {
                    const float* ap = Asb + (wM * WM + mt * 16 + lr) * ASTR + k0 + lc;
                    afP[nb][mt][0] = __float_as_uint(ap[0]);
                    afP[nb][mt][1] = __float_as_uint(ap[8 * ASTR]);
                    afP[nb][mt][2] = __float_as_uint(ap[4]);
                    afP[nb][mt][3] = __float_as_uint(ap[8 * ASTR + 4]);
                }
#pragma unroll
                for (int nt = 0; nt < NT; nt++) {
                    const float* bp = Bsb + (k0 + lc) * BSTR + wN * WN + nt * 8 + lr;
                    bfP[nb][nt][0] = __float_as_uint(bp[0]);
                    bfP[nb][nt][1] = __float_as_uint(bp[4 * BSTR]);
                }
            }
#pragma unroll
            for (int nt = 0; nt < NT; nt++)
#pragma unroll
                for (int mt = 0; mt < MT; mt++)
                    mma_tf32(acc[mt][nt], afP[cb][mt], bfP[cb][nt][0], bfP[cb][nt][1]);
        }

        if (kt + 1 < nk) {
            const int nxt = cur ^ 1;
            float* Asb2 = AsBase + nxt * BM * ASTR;
            float* Bsb2 = BsBase + nxt * BK * BSTR;
#pragma unroll
            for (int q = 0; q < 4; q++) {
                float4 t4 = aR[q];
                t4.x = to_tf32(t4.x); t4.y = to_tf32(t4.y);
                t4.z = to_tf32(t4.z); t4.w = to_tf32(t4.w);
                *(float4*)(Asb2 + am * ASTR + ak0 + q * 4) = t4;
            }
#pragma unroll
            for (int q = 0; q < BQ; q++) {
                float4 t4 = bR[q];
                t4.x = to_tf32(t4.x); t4.y = to_tf32(t4.y);
                t4.z = to_tf32(t4.z); t4.w = to_tf32(t4.w);
                *(float4*)(Bsb2 + (bkr + q * BKR) * BSTR + bnc) = t4;
            }
            __syncthreads();
            cur = nxt;
        }
    }

#pragma unroll
    for (int mt = 0; mt < MT; mt++) {
        const int r0 = bm * BM + wM * WM + mt * 16 + lr;
#pragma unroll
        for (int nt = 0; nt < NT; nt++) {
            const int col = bn * BN + wN * WN + nt * 8 + lc * 2;
            float2 o0, o1;
            o0.x = epi_apply<EPI>(acc[mt][nt][0]);
            o0.y = epi_apply<EPI>(acc[mt][nt][1]);
            o1.x = epi_apply<EPI>(acc[mt][nt][2]);
            o1.y = epi_apply<EPI>(acc[mt][nt][3]);
            *(float2*)(C + (size_t)r0 * N + col) = o0;
            *(float2*)(C + (size_t)(r0 + 8) * N + col) = o1;
        }
    }
}

template <int BN, int EPI, bool MIX>
__global__ void __launch_bounds__(256)
mma_gemm(const float* __restrict__ A, const float* __restrict__ coef,
         const float* __restrict__ B, float* __restrict__ C,
         int M, int N, int K) {
    mma_gemm_body<BN, EPI, MIX>(A, coef, B, C, M, N, K);
}

// merged r/k/v projections: blockIdx.z selects (coef, W, out)
__global__ void __launch_bounds__(256)
rkv3(const float* __restrict__ x,
     const float* cr, const float* ck, const float* cv,
     const float* Wr, const float* Wk, const float* Wv,
     float* r, float* k, float* v) {
    const int z = blockIdx.z;
    const float* coef = (z == 0) ? cr : (z == 1) ? ck : cv;
    const float* B    = (z == 0) ? Wr : (z == 1) ? Wk : Wv;
    float* C          = (z == 0) ? r  : (z == 1) ? k  : v;
    mma_gemm_body<128, EPI_NONE, true>(x, coef, B, C, BT, CC, CC);
}

// merged lora stage-1: blockIdx.z selects (coef, W, out); tanh fused
__global__ void __launch_bounds__(256)
lora3(const float* __restrict__ x,
      const float* cw, const float* ca, const float* cg,
      const float* w1, const float* a1, const float* g1,
      float* hw, float* ha, float* hg) {
    const int z = blockIdx.z;
    const float* coef = (z == 0) ? cw : (z == 1) ? ca : cg;
    const float* B    = (z == 0) ? w1 : (z == 1) ? a1 : g1;
    float* C          = (z == 0) ? hw : (z == 1) ? ha : hg;
    mma_gemm_body<64, EPI_TANH, true>(x, coef, B, C, BT, DLOW, CC);
}

// ---------------------------------------------------------------------------
// decay w and in-context lr a:  one thread per (token, head)
// ---------------------------------------------------------------------------
__global__ void wa_kernel(const float* __restrict__ hw, const float* __restrict__ ha,
                          const float* __restrict__ w2, const float* __restrict__ a2,
                          const float* __restrict__ w0, const float* __restrict__ a0,
                          float* __restrict__ wout, float* __restrict__ aout) {
    const int idx = blockIdx.x * blockDim.x + threadIdx.x;
    const int token = idx >> 4;
    const int h = idx & 15;
    const float* hwr = hw + (size_t)token * 64;
    const float* har = ha + (size_t)token * 64;
    float sw = 0.f, sa = 0.f;
#pragma unroll
    for (int kx = 0; kx < 64; kx++) {
        sw = fmaf(hwr[kx], w2[kx * HH + h], sw);
        sa = fmaf(har[kx], a2[kx * HH + h], sa);
    }
    const float zw = w0[h] + sw;
    wout[idx] = 0.60653065971263342f / (1.f + expf(-zw));   // e^{-0.5} * sigmoid
    aout[idx] = 1.f / (1.f + expf(-(a0[h] + sa)));
}

// ---------------------------------------------------------------------------
// kk = normalize((k*k_k) per head), kv = kk * v * a.  One warp per (token,h).
// ---------------------------------------------------------------------------
__global__ void kv_kernel(const float* __restrict__ k, const float* __restrict__ v,
                          const float* __restrict__ k_k, const float* __restrict__ abuf,
                          float* __restrict__ kkout, float* __restrict__ kvout) {
    const int gw = (blockIdx.x * blockDim.x + threadIdx.x) >> 5;
    const int lane = threadIdx.x & 31;
    const int token = gw >> 4;
    const int h = gw & 15;
    const size_t base = (size_t)token * CC + h * DD;
    const int c0 = h * DD + lane, c1 = c0 + 32;

    float k0 = k[base + lane]       * k_k[c0];
    float k1 = k[base + lane + 32]  * k_k[c1];
    float ss = k0 * k0 + k1 * k1;
#pragma unroll
    for (int o = 16; o; o >>= 1) ss += __shfl_xor_sync(0xffffffffu, ss, o);
    const float inv = 1.f / fmaxf(sqrtf(ss), 1e-12f);
    k0 *= inv; k1 *= inv;
    const float a = abuf[(size_t)token * HH + h];
    const float vv0 = v[base + lane], vv1 = v[base + lane + 32];
    kkout[base + lane]      = k0;
    kkout[base + lane + 32] = k1;
    kvout[base + lane]      = k0 * vv0 * a;
    kvout[base + lane + 32] = k1 * vv1 * a;
}

// ---------------------------------------------------------------------------
// WKV scan: state = state * w_t + kv_t. One block per (b,h), 64 threads.
// ---------------------------------------------------------------------------
__global__ void scan_kernel(const float* __restrict__ kv, const float* __restrict__ wdec,
                            float* __restrict__ wkv) {
    const int bh = blockIdx.x;
    const int b = bh >> 4, h = bh & 15;
    const int d = threadIdx.x;
    const size_t base = (size_t)b * TT * CC + (size_t)h * DD + d;
    const float* kvp = kv + base;
    float* op = wkv + base;
    const float* wp = wdec + (size_t)b * TT * HH + h;
    float state = 0.f;
#pragma unroll 16
    for (int t = 0; t < TT; t++) {
        const float w = wp[(size_t)t * HH];
        const float x = kvp[(size_t)t * CC];
        state = fmaf(state, w, x);
        op[(size_t)t * CC] = state;
    }
}

// ---------------------------------------------------------------------------
// Fused epilogue: bonus + GroupNorm + affine + gate. One warp per (token,h).
// ---------------------------------------------------------------------------
__global__ void epi_kernel(const float* __restrict__ wkv, const float* __restrict__ r,
                           const float* __restrict__ kk, const float* __restrict__ v,
                           const float* __restrict__ r_k, const float* __restrict__ g,
                           const float* __restrict__ lnw, const float* __restrict__ lnb,
                           float* __restrict__ xng) {
    const int gw = (blockIdx.x * blockDim.x + threadIdx.x) >> 5;
    const int lane = threadIdx.x & 31;
    const int token = gw >> 4;
    const int h = gw & 15;
    const size_t base = (size_t)token * CC + h * DD;
    const int c0 = h * DD + lane, c1 = c0 + 32;

    const float s0 = wkv[base + lane],      s1 = wkv[base + lane + 32];
    const float r0 = r[base + lane],        r1 = r[base + lane + 32];
    const float q0 = kk[base + lane],       q1 = kk[base + lane + 32];
    const float v0 = v[base + lane],        v1 = v[base + lane + 32];
    const float g0 = g[base + lane],        g1v = g[base + lane + 32];

    float bsum = r0 * q0 * r_k[c0] + r1 * q1 * r_k[c1];
#pragma unroll
    for (int o = 16; o; o >>= 1) bsum += __shfl_xor_sync(0xffffffffu, bsum, o);

    const float x0 = fmaf(bsum, v0, s0 * r0);
    const float x1 = fmaf(bsum, v1, s1 * r1);

    float ms = x0 + x1;
    float vs = x0 * x0 + x1 * x1;
#pragma unroll
    for (int o = 16; o; o >>= 1) {
        ms += __shfl_xor_sync(0xffffffffu, ms, o);
        vs += __shfl_xor_sync(0xffffffffu, vs, o);
    }
    const float mean = ms * (1.f / 64.f);
    const float var  = vs * (1.f / 64.f) - mean * mean;
    const float rs = rsqrtf(var + 1e-5f);

    xng[base + lane]      = fmaf((x0 - mean) * rs, lnw[c0], lnb[c0]) * g0;
    xng[base + lane + 32] = fmaf((x1 - mean) * rs, lnw[c1], lnb[c1]) * g1v;
}

// ---------------------------------------------------------------------------
// Host launch
// ---------------------------------------------------------------------------
extern "C" void kernel_launch(void* const* d_in, const int* in_sizes, int n_in,
                              void* d_out, int out_size) {
    (void)in_sizes; (void)n_in; (void)out_size;
    const float* x   = (const float*)d_in[0];
    const float* x_r = (const float*)d_in[1];
    const float* x_w = (const float*)d_in[2];
    const float* x_k = (const float*)d_in[3];
    const float* x_v = (const float*)d_in[4];
    const float* x_a = (const float*)d_in[5];
    const float* x_g = (const float*)d_in[6];
    const float* w0  = (const float*)d_in[7];
    const float* w1  = (const float*)d_in[8];
    const float* w2  = (const float*)d_in[9];
    const float* a0  = (const float*)d_in[10];
    const float* a1  = (const float*)d_in[11];
    const float* a2  = (const float*)d_in[12];
    // d_in[13..15] = v0, v1, v2 : mathematically a no-op in the reference
    const float* g1  = (const float*)d_in[16];
    const float* g2  = (const float*)d_in[17];
    const float* k_k = (const float*)d_in[18];
    const float* r_k = (const float*)d_in[19];
    const float* Wr  = (const float*)d_in[20];
    const float* Wk  = (const float*)d_in[21];
    const float* Wv  = (const float*)d_in[22];
    const float* Wo  = (const float*)d_in[23];
    const float* lnw = (const float*)d_in[24];
    const float* lnb = (const float*)d_in[25];
    float* out = (float*)d_out;

    float* scr = nullptr;
    cudaGetSymbolAddress((void**)&scr, g_scr);

    float* rB   = scr + OFF_R;
    float* kB   = scr + OFF_K;      // becomes kk in-place
    float* vB   = scr + OFF_V;
    float* gate = scr + OFF_GATE;   // becomes xng in-place
    float* kvB  = scr + OFF_KV;     // becomes wkv in-place
    float* hw   = scr + OFF_HW;
    float* ha   = scr + OFF_HA;
    float* hg   = scr + OFF_HG;
    float* wd   = scr + OFF_WD;
    float* ab   = scr + OFF_AB;

    constexpr int SM128 = (2 * 128 * 36 + 2 * 32 * 136) * 4;   // 71680
    constexpr int SM64  = (2 * 128 * 36 + 2 * 32 * 72) * 4;    // 55296

    cudaFuncSetAttribute(rkv3,
                         cudaFuncAttributeMaxDynamicSharedMemorySize, SM128);
    cudaFuncSetAttribute(lora3,
                         cudaFuncAttributeMaxDynamicSharedMemorySize, SM64);
    cudaFuncSetAttribute(mma_gemm<128, EPI_SIG, false>,
                         cudaFuncAttributeMaxDynamicSharedMemorySize, SM128);
    cudaFuncSetAttribute(mma_gemm<128, EPI_NONE, false>,
                         cudaFuncAttributeMaxDynamicSharedMemorySize, SM128);

    // 1) big projections r/k/v merged (fused token-shift mix)
    rkv3<<<dim3(8, 128, 3), 256, SM128>>>(x, x_r, x_k, x_v, Wr, Wk, Wv, rB, kB, vB);

    // 2) lora stage 1 merged (tanh fused)
    lora3<<<dim3(1, 128, 3), 256, SM64>>>(x, x_w, x_a, x_g, w1, a1, g1, hw, ha, hg);

    // 3) decay + in-context lr
    wa_kernel<<<(BT * HH) / 256, 256>>>(hw, ha, w2, a2, w0, a0, wd, ab);

    // 4) gate stage 2 (sigmoid fused)
    mma_gemm<128, EPI_SIG, false><<<dim3(8, 128), 256, SM128>>>(
        hg, nullptr, g2, gate, BT, CC, DLOW);

    // 5) kk normalize + kv  (kk overwrites k in-place)
    kv_kernel<<<(BT * HH) / 8, 256>>>(kB, vB, k_k, ab, kB, kvB);

    // 6) WKV recurrence (wkv overwrites kv in-place)
    scan_kernel<<<8 * HH, 64>>>(kvB, wd, kvB);

    // 7) bonus + GroupNorm + gate (xng overwrites gate in-place)
    epi_kernel<<<(BT * HH) / 8, 256>>>(kvB, rB, kB, vB, r_k, gate, lnw, lnb, gate);

    // 8) output projection
    mma_gemm<128, EPI_NONE, false><<<dim3(8, 128), 256, SM128>>>(
        gate, nullptr, Wo, out, BT, CC, CC);
}

// round 14
// speedup vs baseline: 1.2306x; 1.2306x over previous
#include <cuda_runtime.h>
#include <math.h>
#include <stdint.h>

// Problem constants
#define BT  16384   // B*T
#define TT  2048    // T
#define CC  1024    // C
#define HH  16      // heads
#define DD  64      // head dim
#define DLOW 64

// ---------------------------------------------------------------------------
// Scratch (aliased lifetimes, ~322 MB)
// ---------------------------------------------------------------------------
#define S_BIG   ((size_t)BT * CC)
#define OFF_R    ((size_t)0)
#define OFF_K    ((size_t)1 * S_BIG)         // aliases KK
#define OFF_V    ((size_t)2 * S_BIG)
#define OFF_GATE ((size_t)3 * S_BIG)         // aliases XNG
#define OFF_KV   ((size_t)4 * S_BIG)         // aliases WKV
#define OFF_HW   ((size_t)5 * S_BIG)
#define OFF_HA   (OFF_HW + (size_t)BT * 64)
#define OFF_HG   (OFF_HA + (size_t)BT * 64)
#define OFF_WD   (OFF_HG + (size_t)BT * 64)
#define OFF_AB   (OFF_WD + (size_t)BT * HH)
#define SCR_TOTAL (OFF_AB + (size_t)BT * HH)

__device__ float g_scr[SCR_TOTAL];

// ---------------------------------------------------------------------------
// Helpers
// ---------------------------------------------------------------------------
#define EPI_NONE 0
#define EPI_TANH 1
#define EPI_SIG  2

template <int EPI>
__device__ __forceinline__ float epi_apply(float x) {
    if (EPI == EPI_TANH) return tanhf(x);
    if (EPI == EPI_SIG)  return 1.0f / (1.0f + expf(-x));
    return x;
}

__device__ __forceinline__ float to_tf32(float x) {
    uint32_t o;
    asm("cvt.rna.tf32.f32 %0, %1;" : "=r"(o) : "f"(x));
    return __uint_as_float(o);
}

__device__ __forceinline__ void mma_tf32(float* c, const uint32_t* a,
                                         uint32_t b0, uint32_t b1) {
    asm("mma.sync.aligned.m16n8k8.row.col.f32.tf32.tf32.f32 "
        "{%0,%1,%2,%3}, {%4,%5,%6,%7}, {%8,%9}, {%0,%1,%2,%3};"
        : "+f"(c[0]), "+f"(c[1]), "+f"(c[2]), "+f"(c[3])
        : "r"(a[0]), "r"(a[1]), "r"(a[2]), "r"(a[3]), "r"(b0), "r"(b1));
}

// token-shift mix: a = x + (x - x_prev) * coef  (prev = 0 at t == 0)
template <bool MIX>
__device__ __forceinline__ float4 load_a_frag(const float* __restrict__ A,
                                              const float* __restrict__ coef,
                                              int m, int K, int kidx) {
    float4 cur = *(const float4*)(A + (size_t)m * K + kidx);
    if (MIX) {
        float4 pr = make_float4(0.f, 0.f, 0.f, 0.f);
        if ((m & (TT - 1)) != 0)
            pr = *(const float4*)(A + (size_t)(m - 1) * K + kidx);
        float4 cf = *(const float4*)(coef + kidx);
        cur.x = fmaf(cur.x - pr.x, cf.x, cur.x);
        cur.y = fmaf(cur.y - pr.y, cf.y, cur.y);
        cur.z = fmaf(cur.z - pr.z, cf.z, cur.z);
        cur.w = fmaf(cur.w - pr.w, cf.w, cur.w);
    }
    return cur;
}

// ---------------------------------------------------------------------------
// TF32 mma.sync GEMM: C[M,N] = epi(mix(A)[M,K] @ B[K,N]).
// BM=128, BK=32, 256 threads (8 warps). BN in {128, 64}.
// Register-staged double-buffered smem, 1 barrier per K-tile.
// __launch_bounds__(256,2): cap at 128 regs so 2 CTAs co-reside per SM
// (R11 measured 133 regs at 1 CTA -> only ~5 regs of pressure to absorb).
//   As[buf][m][k]  stride 36 ; Bs[buf][k][n] stride BN+8
// ---------------------------------------------------------------------------
template <int BN, int EPI, bool MIX>
__device__ __forceinline__ void
mma_gemm_body(const float* __restrict__ A, const float* __restrict__ coef,
              const float* __restrict__ B, float* __restrict__ C,
              int M, int N, int K) {
    constexpr int BM = 128, BK = 32;
    constexpr int WARPS_N = (BN == 128) ? 4 : 2;
    constexpr int WM = BM / (8 / WARPS_N);
    constexpr int WN = BN / WARPS_N;
    constexpr int MT = WM / 16;
    constexpr int NT = WN / 8;
    constexpr int KS = BK / 8;
    constexpr int ASTR = BK + 4;
    constexpr int BSTR = BN + 8;
    constexpr int BCOL4 = BN / 4;
    constexpr int BKR = 256 / BCOL4;
    constexpr int BQ = BK / BKR;

    extern __shared__ float sm[];
    float* AsBase = sm;
    float* BsBase = sm + 2 * BM * ASTR;

    const int tid = threadIdx.x;
    const int bm = blockIdx.y, bn = blockIdx.x;
    const int wid = tid >> 5, lane = tid & 31;
    const int lr = lane >> 2, lc = lane & 3;
    const int wM = wid / WARPS_N, wN = wid % WARPS_N;

    const int am = tid >> 1;
    const int ak0 = (tid & 1) * 16;
    const int gm = bm * BM + am;
    const int bkr = tid / BCOL4;
    const int bnc = (tid % BCOL4) * 4;

    float acc[MT][NT][4];
#pragma unroll
    for (int i = 0; i < MT; i++)
#pragma unroll
        for (int j = 0; j < NT; j++)
#pragma unroll
            for (int q = 0; q < 4; q++) acc[i][j][q] = 0.f;

    const int nk = K / BK;
    float4 aR[4];
    float4 bR[BQ];

#pragma unroll
    for (int q = 0; q < 4; q++)
        aR[q] = load_a_frag<MIX>(A, coef, gm, K, ak0 + q * 4);
#pragma unroll
    for (int q = 0; q < BQ; q++)
        bR[q] = *(const float4*)(B + (size_t)(bkr + q * BKR) * N + bn * BN + bnc);

    {
#pragma unroll
        for (int q = 0; q < 4; q++) {
            float4 t4 = aR[q];
            t4.x = to_tf32(t4.x); t4.y = to_tf32(t4.y);
            t4.z = to_tf32(t4.z); t4.w = to_tf32(t4.w);
            *(float4*)(AsBase + am * ASTR + ak0 + q * 4) = t4;
        }
#pragma unroll
        for (int q = 0; q < BQ; q++) {
            float4 t4 = bR[q];
            t4.x = to_tf32(t4.x); t4.y = to_tf32(t4.y);
            t4.z = to_tf32(t4.z); t4.w = to_tf32(t4.w);
            *(float4*)(BsBase + (bkr + q * BKR) * BSTR + bnc) = t4;
        }
    }
    __syncthreads();

    int cur = 0;
    for (int kt = 0; kt < nk; kt++) {
        if (kt + 1 < nk) {
            const int kb = (kt + 1) * BK;
#pragma unroll
            for (int q = 0; q < 4; q++)
                aR[q] = load_a_frag<MIX>(A, coef, gm, K, kb + ak0 + q * 4);
#pragma unroll
            for (int q = 0; q < BQ; q++)
                bR[q] = *(const float4*)(B + (size_t)(kb + bkr + q * BKR) * N + bn * BN + bnc);
        }

        const float* Asb = AsBase + cur * BM * ASTR;
        const float* Bsb = BsBase + cur * BK * BSTR;

        // ---- fragment double-buffered MMA loop ----
        uint32_t afP[2][MT][4];
        uint32_t bfP[2][NT][2];
#pragma unroll
        for (int mt = 0; mt < MT; mt++) {
            const float* ap = Asb + (wM * WM + mt * 16 + lr) * ASTR + lc;
            afP[0][mt][0] = __float_as_uint(ap[0]);
            afP[0][mt][1] = __float_as_uint(ap[8 * ASTR]);
            afP[0][mt][2] = __float_as_uint(ap[4]);
            afP[0][mt][3] = __float_as_uint(ap[8 * ASTR + 4]);
        }
#pragma unroll
        for (int nt = 0; nt < NT; nt++) {
            const float* bp = Bsb + lc * BSTR + wN * WN + nt * 8 + lr;
            bfP[0][nt][0] = __float_as_uint(bp[0]);
            bfP[0][nt][1] = __float_as_uint(bp[4 * BSTR]);
        }
#pragma unroll
        for (int ks = 0; ks < KS; ks++) {
            const int cb = ks & 1;
            const int nb = cb ^ 1;
            if (ks + 1 < KS) {
                const int k0 = (ks + 1) * 8;
#pragma unroll
                for (int mt = 0; mt < MT; mt++) {
                    const float* ap = Asb + (wM * WM + mt * 16 + lr) * ASTR + k0 + lc;
                    afP[nb][mt][0] = __float_as_uint(ap[0]);
                    afP[nb][mt][1] = __float_as_uint(ap[8 * ASTR]);
                    afP[nb][mt][2] = __float_as_uint(ap[4]);
                    afP[nb][mt][3] = __float_as_uint(ap[8 * ASTR + 4]);
                }
#pragma unroll
                for (int nt = 0; nt < NT; nt++) {
                    const float* bp = Bsb + (k0 + lc) * BSTR + wN * WN + nt * 8 + lr;
                    bfP[nb][nt][0] = __float_as_uint(bp[0]);
                    bfP[nb][nt][1] = __float_as_uint(bp[4 * BSTR]);
                }
            }
#pragma unroll
            for (int nt = 0; nt < NT; nt++)
#pragma unroll
                for (int mt = 0; mt < MT; mt++)
                    mma_tf32(acc[mt][nt], afP[cb][mt], bfP[cb][nt][0], bfP[cb][nt][1]);
        }

        if (kt + 1 < nk) {
            const int nxt = cur ^ 1;
            float* Asb2 = AsBase + nxt * BM * ASTR;
            float* Bsb2 = BsBase + nxt * BK * BSTR;
#pragma unroll
            for (int q = 0; q < 4; q++) {
                float4 t4 = aR[q];
                t4.x = to_tf32(t4.x); t4.y = to_tf32(t4.y);
                t4.z = to_tf32(t4.z); t4.w = to_tf32(t4.w);
                *(float4*)(Asb2 + am * ASTR + ak0 + q * 4) = t4;
            }
#pragma unroll
            for (int q = 0; q < BQ; q++) {
                float4 t4 = bR[q];
                t4.x = to_tf32(t4.x); t4.y = to_tf32(t4.y);
                t4.z = to_tf32(t4.z); t4.w = to_tf32(t4.w);
                *(float4*)(Bsb2 + (bkr + q * BKR) * BSTR + bnc) = t4;
            }
            __syncthreads();
            cur = nxt;
        }
    }

#pragma unroll
    for (int mt = 0; mt < MT; mt++) {
        const int r0 = bm * BM + wM * WM + mt * 16 + lr;
#pragma unroll
        for (int nt = 0; nt < NT; nt++) {
            const int col = bn * BN + wN * WN + nt * 8 + lc * 2;
            float2 o0, o1;
            o0.x = epi_apply<EPI>(acc[mt][nt][0]);
            o0.y = epi_apply<EPI>(acc[mt][nt][1]);
            o1.x = epi_apply<EPI>(acc[mt][nt][2]);
            o1.y = epi_apply<EPI>(acc[mt][nt][3]);
            *(float2*)(C + (size_t)r0 * N + col) = o0;
            *(float2*)(C + (size_t)(r0 + 8) * N + col) = o1;
        }
    }
}

template <int BN, int EPI, bool MIX>
__global__ void __launch_bounds__(256, 2)
mma_gemm(const float* __restrict__ A, const float* __restrict__ coef,
         const float* __restrict__ B, float* __restrict__ C,
         int M, int N, int K) {
    mma_gemm_body<BN, EPI, MIX>(A, coef, B, C, M, N, K);
}

// merged r/k/v projections: blockIdx.z selects (coef, W, out)
__global__ void __launch_bounds__(256, 2)
rkv3(const float* __restrict__ x,
     const float* cr, const float* ck, const float* cv,
     const float* Wr, const float* Wk, const float* Wv,
     float* r, float* k, float* v) {
    const int z = blockIdx.z;
    const float* coef = (z == 0) ? cr : (z == 1) ? ck : cv;
    const float* B    = (z == 0) ? Wr : (z == 1) ? Wk : Wv;
    float* C          = (z == 0) ? r  : (z == 1) ? k  : v;
    mma_gemm_body<128, EPI_NONE, true>(x, coef, B, C, BT, CC, CC);
}

// merged lora stage-1: blockIdx.z selects (coef, W, out); tanh fused
__global__ void __launch_bounds__(256, 2)
lora3(const float* __restrict__ x,
      const float* cw, const float* ca, const float* cg,
      const float* w1, const float* a1, const float* g1,
      float* hw, float* ha, float* hg) {
    const int z = blockIdx.z;
    const float* coef = (z == 0) ? cw : (z == 1) ? ca : cg;
    const float* B    = (z == 0) ? w1 : (z == 1) ? a1 : g1;
    float* C          = (z == 0) ? hw : (z == 1) ? ha : hg;
    mma_gemm_body<64, EPI_TANH, true>(x, coef, B, C, BT, DLOW, CC);
}

// ---------------------------------------------------------------------------
// decay w and in-context lr a:  one thread per (token, head)
// ---------------------------------------------------------------------------
__global__ void wa_kernel(const float* __restrict__ hw, const float* __restrict__ ha,
                          const float* __restrict__ w2, const float* __restrict__ a2,
                          const float* __restrict__ w0, const float* __restrict__ a0,
                          float* __restrict__ wout, float* __restrict__ aout) {
    const int idx = blockIdx.x * blockDim.x + threadIdx.x;
    const int token = idx >> 4;
    const int h = idx & 15;
    const float* hwr = hw + (size_t)token * 64;
    const float* har = ha + (size_t)token * 64;
    float sw = 0.f, sa = 0.f;
#pragma unroll
    for (int kx = 0; kx < 64; kx++) {
        sw = fmaf(hwr[kx], w2[kx * HH + h], sw);
        sa = fmaf(har[kx], a2[kx * HH + h], sa);
    }
    const float zw = w0[h] + sw;
    wout[idx] = 0.60653065971263342f / (1.f + expf(-zw));   // e^{-0.5} * sigmoid
    aout[idx] = 1.f / (1.f + expf(-(a0[h] + sa)));
}

// ---------------------------------------------------------------------------
// kk = normalize((k*k_k) per head), kv = kk * v * a.  One warp per (token,h).
// ---------------------------------------------------------------------------
__global__ void kv_kernel(const float* __restrict__ k, const float* __restrict__ v,
                          const float* __restrict__ k_k, const float* __restrict__ abuf,
                          float* __restrict__ kkout, float* __restrict__ kvout) {
    const int gw = (blockIdx.x * blockDim.x + threadIdx.x) >> 5;
    const int lane = threadIdx.x & 31;
    const int token = gw >> 4;
    const int h = gw & 15;
    const size_t base = (size_t)token * CC + h * DD;
    const int c0 = h * DD + lane, c1 = c0 + 32;

    float k0 = k[base + lane]       * k_k[c0];
    float k1 = k[base + lane + 32]  * k_k[c1];
    float ss = k0 * k0 + k1 * k1;
#pragma unroll
    for (int o = 16; o; o >>= 1) ss += __shfl_xor_sync(0xffffffffu, ss, o);
    const float inv = 1.f / fmaxf(sqrtf(ss), 1e-12f);
    k0 *= inv; k1 *= inv;
    const float a = abuf[(size_t)token * HH + h];
    const float vv0 = v[base + lane], vv1 = v[base + lane + 32];
    kkout[base + lane]      = k0;
    kkout[base + lane + 32] = k1;
    kvout[base + lane]      = k0 * vv0 * a;
    kvout[base + lane + 32] = k1 * vv1 * a;
}

// ---------------------------------------------------------------------------
// WKV scan: state = state * w_t + kv_t. One block per (b,h), 64 threads.
// ---------------------------------------------------------------------------
__global__ void scan_kernel(const float* __restrict__ kv, const float* __restrict__ wdec,
                            float* __restrict__ wkv) {
    const int bh = blockIdx.x;
    const int b = bh >> 4, h = bh & 15;
    const int d = threadIdx.x;
    const size_t base = (size_t)b * TT * CC + (size_t)h * DD + d;
    const float* kvp = kv + base;
    float* op = wkv + base;
    const float* wp = wdec + (size_t)b * TT * HH + h;
    float state = 0.f;
#pragma unroll 16
    for (int t = 0; t < TT; t++) {
        const float w = wp[(size_t)t * HH];
        const float x = kvp[(size_t)t * CC];
        state = fmaf(state, w, x);
        op[(size_t)t * CC] = state;
    }
}

// ---------------------------------------------------------------------------
// Fused epilogue: bonus + GroupNorm + affine + gate. One warp per (token,h).
// ---------------------------------------------------------------------------
__global__ void epi_kernel(const float* __restrict__ wkv, const float* __restrict__ r,
                           const float* __restrict__ kk, const float* __restrict__ v,
                           const float* __restrict__ r_k, const float* __restrict__ g,
                           const float* __restrict__ lnw, const float* __restrict__ lnb,
                           float* __restrict__ xng) {
    const int gw = (blockIdx.x * blockDim.x + threadIdx.x) >> 5;
    const int lane = threadIdx.x & 31;
    const int token = gw >> 4;
    const int h = gw & 15;
    const size_t base = (size_t)token * CC + h * DD;
    const int c0 = h * DD + lane, c1 = c0 + 32;

    const float s0 = wkv[base + lane],      s1 = wkv[base + lane + 32];
    const float r0 = r[base + lane],        r1 = r[base + lane + 32];
    const float q0 = kk[base + lane],       q1 = kk[base + lane + 32];
    const float v0 = v[base + lane],        v1 = v[base + lane + 32];
    const float g0 = g[base + lane],        g1v = g[base + lane + 32];

    float bsum = r0 * q0 * r_k[c0] + r1 * q1 * r_k[c1];
#pragma unroll
    for (int o = 16; o; o >>= 1) bsum += __shfl_xor_sync(0xffffffffu, bsum, o);

    const float x0 = fmaf(bsum, v0, s0 * r0);
    const float x1 = fmaf(bsum, v1, s1 * r1);

    float ms = x0 + x1;
    float vs = x0 * x0 + x1 * x1;
#pragma unroll
    for (int o = 16; o; o >>= 1) {
        ms += __shfl_xor_sync(0xffffffffu, ms, o);
        vs += __shfl_xor_sync(0xffffffffu, vs, o);
    }
    const float mean = ms * (1.f / 64.f);
    const float var  = vs * (1.f / 64.f) - mean * mean;
    const float rs = rsqrtf(var + 1e-5f);

    xng[base + lane]      = fmaf((x0 - mean) * rs, lnw[c0], lnb[c0]) * g0;
    xng[base + lane + 32] = fmaf((x1 - mean) * rs, lnw[c1], lnb[c1]) * g1v;
}

// ---------------------------------------------------------------------------
// Host launch
// ---------------------------------------------------------------------------
extern "C" void kernel_launch(void* const* d_in, const int* in_sizes, int n_in,
                              void* d_out, int out_size) {
    (void)in_sizes; (void)n_in; (void)out_size;
    const float* x   = (const float*)d_in[0];
    const float* x_r = (const float*)d_in[1];
    const float* x_w = (const float*)d_in[2];
    const float* x_k = (const float*)d_in[3];
    const float* x_v = (const float*)d_in[4];
    const float* x_a = (const float*)d_in[5];
    const float* x_g = (const float*)d_in[6];
    const float* w0  = (const float*)d_in[7];
    const float* w1  = (const float*)d_in[8];
    const float* w2  = (const float*)d_in[9];
    const float* a0  = (const float*)d_in[10];
    const float* a1  = (const float*)d_in[11];
    const float* a2  = (const float*)d_in[12];
    // d_in[13..15] = v0, v1, v2 : mathematically a no-op in the reference
    const float* g1  = (const float*)d_in[16];
    const float* g2  = (const float*)d_in[17];
    const float* k_k = (const float*)d_in[18];
    const float* r_k = (const float*)d_in[19];
    const float* Wr  = (const float*)d_in[20];
    const float* Wk  = (const float*)d_in[21];
    const float* Wv  = (const float*)d_in[22];
    const float* Wo  = (const float*)d_in[23];
    const float* lnw = (const float*)d_in[24];
    const float* lnb = (const float*)d_in[25];
    float* out = (float*)d_out;

    float* scr = nullptr;
    cudaGetSymbolAddress((void**)&scr, g_scr);

    float* rB   = scr + OFF_R;
    float* kB   = scr + OFF_K;      // becomes kk in-place
    float* vB   = scr + OFF_V;
    float* gate = scr + OFF_GATE;   // becomes xng in-place
    float* kvB  = scr + OFF_KV;     // becomes wkv in-place
    float* hw   = scr + OFF_HW;
    float* ha   = scr + OFF_HA;
    float* hg   = scr + OFF_HG;
    float* wd   = scr + OFF_WD;
    float* ab   = scr + OFF_AB;

    constexpr int SM128 = (2 * 128 * 36 + 2 * 32 * 136) * 4;   // 71680
    constexpr int SM64  = (2 * 128 * 36 + 2 * 32 * 72) * 4;    // 55296

    cudaFuncSetAttribute(rkv3,
                         cudaFuncAttributeMaxDynamicSharedMemorySize, SM128);
    cudaFuncSetAttribute(lora3,
                         cudaFuncAttributeMaxDynamicSharedMemorySize, SM64);
    cudaFuncSetAttribute(mma_gemm<128, EPI_SIG, false>,
                         cudaFuncAttributeMaxDynamicSharedMemorySize, SM128);
    cudaFuncSetAttribute(mma_gemm<128, EPI_NONE, false>,
                         cudaFuncAttributeMaxDynamicSharedMemorySize, SM128);

    // 1) big projections r/k/v merged (fused token-shift mix)
    rkv3<<<dim3(8, 128, 3), 256, SM128>>>(x, x_r, x_k, x_v, Wr, Wk, Wv, rB, kB, vB);

    // 2) lora stage 1 merged (tanh fused)
    lora3<<<dim3(1, 128, 3), 256, SM64>>>(x, x_w, x_a, x_g, w1, a1, g1, hw, ha, hg);

    // 3) decay + in-context lr
    wa_kernel<<<(BT * HH) / 256, 256>>>(hw, ha, w2, a2, w0, a0, wd, ab);

    // 4) gate stage 2 (sigmoid fused)
    mma_gemm<128, EPI_SIG, false><<<dim3(8, 128), 256, SM128>>>(
        hg, nullptr, g2, gate, BT, CC, DLOW);

    // 5) kk normalize + kv  (kk overwrites k in-place)
    kv_kernel<<<(BT * HH) / 8, 256>>>(kB, vB, k_k, ab, kB, kvB);

    // 6) WKV recurrence (wkv overwrites kv in-place)
    scan_kernel<<<8 * HH, 64>>>(kvB, wd, kvB);

    // 7) bonus + GroupNorm + gate (xng overwrites gate in-place)
    epi_kernel<<<(BT * HH) / 8, 256>>>(kvB, rB, kB, vB, r_k, gate, lnw, lnb, gate);

    // 8) output projection
    mma_gemm<128, EPI_NONE, false><<<dim3(8, 128), 256, SM128>>>(
        gate, nullptr, Wo, out, BT, CC, CC);
}

// round 15
// speedup vs baseline: 1.2518x; 1.0172x over previous
#include <cuda_runtime.h>
#include <math.h>
#include <stdint.h>

// Problem constants
#define BT  16384   // B*T
#define TT  2048    // T
#define CC  1024    // C
#define HH  16      // heads
#define DD  64      // head dim
#define DLOW 64

// ---------------------------------------------------------------------------
// Scratch (aliased lifetimes, ~338 MB)
// ---------------------------------------------------------------------------
#define S_BIG   ((size_t)BT * CC)
#define OFF_R    ((size_t)0)
#define OFF_K    ((size_t)1 * S_BIG)         // aliases KK
#define OFF_V    ((size_t)2 * S_BIG)
#define OFF_GATE ((size_t)3 * S_BIG)         // aliases XNG
#define OFF_KV   ((size_t)4 * S_BIG)         // aliases WKV
#define OFF_HW   ((size_t)5 * S_BIG)
#define OFF_HA   (OFF_HW + (size_t)BT * 64)
#define OFF_HG   (OFF_HA + (size_t)BT * 64)
#define OFF_WD   (OFF_HG + (size_t)BT * 64)
#define OFF_AB   (OFF_WD + (size_t)BT * HH)
#define OFF_WT0  (OFF_AB + (size_t)BT * HH)   // tf32-pre-rounded big weights
#define OFF_WT1  (OFF_WT0 + (size_t)CC * CC)
#define OFF_WT2  (OFF_WT1 + (size_t)CC * CC)
#define OFF_WT3  (OFF_WT2 + (size_t)CC * CC)
#define SCR_TOTAL (OFF_WT3 + (size_t)CC * CC)

__device__ float g_scr[SCR_TOTAL];

// ---------------------------------------------------------------------------
// Helpers
// ---------------------------------------------------------------------------
#define EPI_NONE 0
#define EPI_TANH 1
#define EPI_SIG  2

template <int EPI>
__device__ __forceinline__ float epi_apply(float x) {
    if (EPI == EPI_TANH) return tanhf(x);
    if (EPI == EPI_SIG)  return 1.0f / (1.0f + expf(-x));
    return x;
}

__device__ __forceinline__ float to_tf32(float x) {
    uint32_t o;
    asm("cvt.rna.tf32.f32 %0, %1;" : "=r"(o) : "f"(x));
    return __uint_as_float(o);
}

__device__ __forceinline__ void mma_tf32(float* c, const uint32_t* a,
                                         uint32_t b0, uint32_t b1) {
    asm("mma.sync.aligned.m16n8k8.row.col.f32.tf32.tf32.f32 "
        "{%0,%1,%2,%3}, {%4,%5,%6,%7}, {%8,%9}, {%0,%1,%2,%3};"
        : "+f"(c[0]), "+f"(c[1]), "+f"(c[2]), "+f"(c[3])
        : "r"(a[0]), "r"(a[1]), "r"(a[2]), "r"(a[3]), "r"(b0), "r"(b1));
}

__device__ __forceinline__ uint32_t smem_u32(const void* p) {
    uint32_t a;
    asm("{ .reg .u64 t; cvta.to.shared.u64 t, %1; cvt.u32.u64 %0, t; }"
        : "=r"(a) : "l"(p));
    return a;
}

__device__ __forceinline__ void cp_async16(uint32_t dst, const void* src) {
    asm volatile("cp.async.cg.shared.global [%0], [%1], 16;"
                 :: "r"(dst), "l"(src));
}
#define CP_COMMIT() asm volatile("cp.async.commit_group;")
#define CP_WAIT0()  asm volatile("cp.async.wait_group 0;")

// token-shift mix: a = x + (x - x_prev) * coef  (prev = 0 at t == 0)
template <bool MIX>
__device__ __forceinline__ float4 load_a_frag(const float* __restrict__ A,
                                              const float* __restrict__ coef,
                                              int m, int K, int kidx) {
    float4 cur = *(const float4*)(A + (size_t)m * K + kidx);
    if (MIX) {
        float4 pr = make_float4(0.f, 0.f, 0.f, 0.f);
        if ((m & (TT - 1)) != 0)
            pr = *(const float4*)(A + (size_t)(m - 1) * K + kidx);
        float4 cf = *(const float4*)(coef + kidx);
        cur.x = fmaf(cur.x - pr.x, cf.x, cur.x);
        cur.y = fmaf(cur.y - pr.y, cf.y, cur.y);
        cur.z = fmaf(cur.z - pr.z, cf.z, cur.z);
        cur.w = fmaf(cur.w - pr.w, cf.w, cur.w);
    }
    return cur;
}

// ---------------------------------------------------------------------------
// tf32 (rna) pre-round of the 4 big weights — single merged launch.
// ---------------------------------------------------------------------------
__global__ void tfround4(const float* __restrict__ s0, const float* __restrict__ s1,
                         const float* __restrict__ s2, const float* __restrict__ s3,
                         float* __restrict__ d0, float* __restrict__ d1,
                         float* __restrict__ d2, float* __restrict__ d3) {
    const int z = blockIdx.y;
    const float* s = (z == 0) ? s0 : (z == 1) ? s1 : (z == 2) ? s2 : s3;
    float* d       = (z == 0) ? d0 : (z == 1) ? d1 : (z == 2) ? d2 : d3;
    const int i = (blockIdx.x * blockDim.x + threadIdx.x) * 4;
    float4 v = *(const float4*)(s + i);
    v.x = to_tf32(v.x); v.y = to_tf32(v.y);
    v.z = to_tf32(v.z); v.w = to_tf32(v.w);
    *(float4*)(d + i) = v;
}

// ---------------------------------------------------------------------------
// TF32 mma.sync GEMM: C[M,N] = epi(mix(A)[M,K] @ B[K,N]).
// BM=128, BK=32, 256 threads (8 warps). BN in {128, 64}.
// A: register-staged (mix fused, rna STS). B: cp.async when BCP (weights
// pre-rounded), else register-staged with in-kernel rna.
// __launch_bounds__(256,2) — 2 CTAs/SM (RF exactly full at 128 regs).
//   As[buf][m][k] stride 36 ; Bs[buf][k][n] stride BN+8 (16B-aligned rows)
// ---------------------------------------------------------------------------
template <int BN, int EPI, bool MIX, bool BCP>
__device__ __forceinline__ void
mma_gemm_body(const float* __restrict__ A, const float* __restrict__ coef,
              const float* __restrict__ B, float* __restrict__ C,
              int M, int N, int K) {
    constexpr int BM = 128, BK = 32;
    constexpr int WARPS_N = (BN == 128) ? 4 : 2;
    constexpr int WM = BM / (8 / WARPS_N);
    constexpr int WN = BN / WARPS_N;
    constexpr int MT = WM / 16;
    constexpr int NT = WN / 8;
    constexpr int KS = BK / 8;
    constexpr int ASTR = BK + 4;
    constexpr int BSTR = BN + 8;               // 136/72 floats -> 544/288B (16B mult)
    constexpr int BCOL4 = BN / 4;
    constexpr int BKR = 256 / BCOL4;
    constexpr int BQ = BK / BKR;

    extern __shared__ float sm[];
    float* AsBase = sm;
    float* BsBase = sm + 2 * BM * ASTR;
    const uint32_t bs_u32 = smem_u32(BsBase);

    const int tid = threadIdx.x;
    const int bm = blockIdx.y, bn = blockIdx.x;
    const int wid = tid >> 5, lane = tid & 31;
    const int lr = lane >> 2, lc = lane & 3;
    const int wM = wid / WARPS_N, wN = wid % WARPS_N;

    const int am = tid >> 1;
    const int ak0 = (tid & 1) * 16;
    const int gm = bm * BM + am;
    const int bkr = tid / BCOL4;
    const int bnc = (tid % BCOL4) * 4;

    float acc[MT][NT][4];
#pragma unroll
    for (int i = 0; i < MT; i++)
#pragma unroll
        for (int j = 0; j < NT; j++)
#pragma unroll
            for (int q = 0; q < 4; q++) acc[i][j][q] = 0.f;

    const int nk = K / BK;
    float4 aR[4];
    float4 bR[BCP ? 1 : BQ];

    // --- prologue: tile 0 ---
    if (BCP) {
#pragma unroll
        for (int q = 0; q < BQ; q++)
            cp_async16(bs_u32 + (uint32_t)((bkr + q * BKR) * BSTR + bnc) * 4,
                       B + (size_t)(bkr + q * BKR) * N + bn * BN + bnc);
        CP_COMMIT();
    } else {
#pragma unroll
        for (int q = 0; q < BQ; q++)
            bR[q] = *(const float4*)(B + (size_t)(bkr + q * BKR) * N + bn * BN + bnc);
    }
#pragma unroll
    for (int q = 0; q < 4; q++)
        aR[q] = load_a_frag<MIX>(A, coef, gm, K, ak0 + q * 4);

#pragma unroll
    for (int q = 0; q < 4; q++) {
        float4 t4 = aR[q];
        t4.x = to_tf32(t4.x); t4.y = to_tf32(t4.y);
        t4.z = to_tf32(t4.z); t4.w = to_tf32(t4.w);
        *(float4*)(AsBase + am * ASTR + ak0 + q * 4) = t4;
    }
    if (!BCP) {
#pragma unroll
        for (int q = 0; q < BQ; q++) {
            float4 t4 = bR[q];
            t4.x = to_tf32(t4.x); t4.y = to_tf32(t4.y);
            t4.z = to_tf32(t4.z); t4.w = to_tf32(t4.w);
            *(float4*)(BsBase + (bkr + q * BKR) * BSTR + bnc) = t4;
        }
    }
    if (BCP) CP_WAIT0();
    __syncthreads();

    int cur = 0;
    for (int kt = 0; kt < nk; kt++) {
        if (kt + 1 < nk) {
            const int kb = (kt + 1) * BK;
            if (BCP) {
                const uint32_t bdst = bs_u32 + (uint32_t)((cur ^ 1) * BK * BSTR) * 4;
#pragma unroll
                for (int q = 0; q < BQ; q++)
                    cp_async16(bdst + (uint32_t)((bkr + q * BKR) * BSTR + bnc) * 4,
                               B + (size_t)(kb + bkr + q * BKR) * N + bn * BN + bnc);
                CP_COMMIT();
            } else {
#pragma unroll
                for (int q = 0; q < BQ; q++)
                    bR[q] = *(const float4*)(B + (size_t)(kb + bkr + q * BKR) * N + bn * BN + bnc);
            }
#pragma unroll
            for (int q = 0; q < 4; q++)
                aR[q] = load_a_frag<MIX>(A, coef, gm, K, kb + ak0 + q * 4);
        }

        const float* Asb = AsBase + cur * BM * ASTR;
        const float* Bsb = BsBase + cur * BK * BSTR;

        // ---- fragment double-buffered MMA loop ----
        uint32_t afP[2][MT][4];
        uint32_t bfP[2][NT][2];
#pragma unroll
        for (int mt = 0; mt < MT; mt++) {
            const float* ap = Asb + (wM * WM + mt * 16 + lr) * ASTR + lc;
            afP[0][mt][0] = __float_as_uint(ap[0]);
            afP[0][mt][1] = __float_as_uint(ap[8 * ASTR]);
            afP[0][mt][2] = __float_as_uint(ap[4]);
            afP[0][mt][3] = __float_as_uint(ap[8 * ASTR + 4]);
        }
#pragma unroll
        for (int nt = 0; nt < NT; nt++) {
            const float* bp = Bsb + lc * BSTR + wN * WN + nt * 8 + lr;
            bfP[0][nt][0] = __float_as_uint(bp[0]);
            bfP[0][nt][1] = __float_as_uint(bp[4 * BSTR]);
        }
#pragma unroll
        for (int ks = 0; ks < KS; ks++) {
            const int cb = ks & 1;
            const int nb = cb ^ 1;
            if (ks + 1 < KS) {
                const int k0 = (ks + 1) * 8;
#pragma unroll
                for (int mt = 0; mt < MT; mt++) {
                    const float* ap = Asb + (wM * WM + mt * 16 + lr) * ASTR + k0 + lc;
                    afP[nb][mt][0] = __float_as_uint(ap[0]);
                    afP[nb][mt][1] = __float_as_uint(ap[8 * ASTR]);
                    afP[nb][mt][2] = __float_as_uint(ap[4]);
                    afP[nb][mt][3] = __float_as_uint(ap[8 * ASTR + 4]);
                }
#pragma unroll
                for (int nt = 0; nt < NT; nt++) {
                    const float* bp = Bsb + (k0 + lc) * BSTR + wN * WN + nt * 8 + lr;
                    bfP[nb][nt][0] = __float_as_uint(bp[0]);
                    bfP[nb][nt][1] = __float_as_uint(bp[4 * BSTR]);
                }
            }
#pragma unroll
            for (int nt = 0; nt < NT; nt++)
#pragma unroll
                for (int mt = 0; mt < MT; mt++)
                    mma_tf32(acc[mt][nt], afP[cb][mt], bfP[cb][nt][0], bfP[cb][nt][1]);
        }

        if (kt + 1 < nk) {
            const int nxt = cur ^ 1;
            float* Asb2 = AsBase + nxt * BM * ASTR;
#pragma unroll
            for (int q = 0; q < 4; q++) {
                float4 t4 = aR[q];
                t4.x = to_tf32(t4.x); t4.y = to_tf32(t4.y);
                t4.z = to_tf32(t4.z); t4.w = to_tf32(t4.w);
                *(float4*)(Asb2 + am * ASTR + ak0 + q * 4) = t4;
            }
            if (!BCP) {
                float* Bsb2 = BsBase + nxt * BK * BSTR;
#pragma unroll
                for (int q = 0; q < BQ; q++) {
                    float4 t4 = bR[q];
                    t4.x = to_tf32(t4.x); t4.y = to_tf32(t4.y);
                    t4.z = to_tf32(t4.z); t4.w = to_tf32(t4.w);
                    *(float4*)(Bsb2 + (bkr + q * BKR) * BSTR + bnc) = t4;
                }
            }
            if (BCP) CP_WAIT0();
            __syncthreads();
            cur = nxt;
        }
    }

#pragma unroll
    for (int mt = 0; mt < MT; mt++) {
        const int r0 = bm * BM + wM * WM + mt * 16 + lr;
#pragma unroll
        for (int nt = 0; nt < NT; nt++) {
            const int col = bn * BN + wN * WN + nt * 8 + lc * 2;
            float2 o0, o1;
            o0.x = epi_apply<EPI>(acc[mt][nt][0]);
            o0.y = epi_apply<EPI>(acc[mt][nt][1]);
            o1.x = epi_apply<EPI>(acc[mt][nt][2]);
            o1.y = epi_apply<EPI>(acc[mt][nt][3]);
            *(float2*)(C + (size_t)r0 * N + col) = o0;
            *(float2*)(C + (size_t)(r0 + 8) * N + col) = o1;
        }
    }
}

template <int BN, int EPI, bool MIX, bool BCP>
__global__ void __launch_bounds__(256, 2)
mma_gemm(const float* __restrict__ A, const float* __restrict__ coef,
         const float* __restrict__ B, float* __restrict__ C,
         int M, int N, int K) {
    mma_gemm_body<BN, EPI, MIX, BCP>(A, coef, B, C, M, N, K);
}

// merged r/k/v projections: blockIdx.z selects (coef, W, out); B via cp.async
__global__ void __launch_bounds__(256, 2)
rkv3(const float* __restrict__ x,
     const float* cr, const float* ck, const float* cv,
     const float* Wr, const float* Wk, const float* Wv,
     float* r, float* k, float* v) {
    const int z = blockIdx.z;
    const float* coef = (z == 0) ? cr : (z == 1) ? ck : cv;
    const float* B    = (z == 0) ? Wr : (z == 1) ? Wk : Wv;
    float* C          = (z == 0) ? r  : (z == 1) ? k  : v;
    mma_gemm_body<128, EPI_NONE, true, true>(x, coef, B, C, BT, CC, CC);
}

// merged lora stage-1: blockIdx.z selects (coef, W, out); tanh fused
__global__ void __launch_bounds__(256, 2)
lora3(const float* __restrict__ x,
      const float* cw, const float* ca, const float* cg,
      const float* w1, const float* a1, const float* g1,
      float* hw, float* ha, float* hg) {
    const int z = blockIdx.z;
    const float* coef = (z == 0) ? cw : (z == 1) ? ca : cg;
    const float* B    = (z == 0) ? w1 : (z == 1) ? a1 : g1;
    float* C          = (z == 0) ? hw : (z == 1) ? ha : hg;
    mma_gemm_body<64, EPI_TANH, true, false>(x, coef, B, C, BT, DLOW, CC);
}

// ---------------------------------------------------------------------------
// decay w and in-context lr a:  one thread per (token, head)
// ---------------------------------------------------------------------------
__global__ void wa_kernel(const float* __restrict__ hw, const float* __restrict__ ha,
                          const float* __restrict__ w2, const float* __restrict__ a2,
                          const float* __restrict__ w0, const float* __restrict__ a0,
                          float* __restrict__ wout, float* __restrict__ aout) {
    const int idx = blockIdx.x * blockDim.x + threadIdx.x;
    const int token = idx >> 4;
    const int h = idx & 15;
    const float* hwr = hw + (size_t)token * 64;
    const float* har = ha + (size_t)token * 64;
    float sw = 0.f, sa = 0.f;
#pragma unroll
    for (int kx = 0; kx < 64; kx++) {
        sw = fmaf(hwr[kx], w2[kx * HH + h], sw);
        sa = fmaf(har[kx], a2[kx * HH + h], sa);
    }
    const float zw = w0[h] + sw;
    wout[idx] = 0.60653065971263342f / (1.f + expf(-zw));   // e^{-0.5} * sigmoid
    aout[idx] = 1.f / (1.f + expf(-(a0[h] + sa)));
}

// ---------------------------------------------------------------------------
// kk = normalize((k*k_k) per head), kv = kk * v * a.  One warp per (token,h).
// ---------------------------------------------------------------------------
__global__ void kv_kernel(const float* __restrict__ k, const float* __restrict__ v,
                          const float* __restrict__ k_k, const float* __restrict__ abuf,
                          float* __restrict__ kkout, float* __restrict__ kvout) {
    const int gw = (blockIdx.x * blockDim.x + threadIdx.x) >> 5;
    const int lane = threadIdx.x & 31;
    const int token = gw >> 4;
    const int h = gw & 15;
    const size_t base = (size_t)token * CC + h * DD;
    const int c0 = h * DD + lane, c1 = c0 + 32;

    float k0 = k[base + lane]       * k_k[c0];
    float k1 = k[base + lane + 32]  * k_k[c1];
    float ss = k0 * k0 + k1 * k1;
#pragma unroll
    for (int o = 16; o; o >>= 1) ss += __shfl_xor_sync(0xffffffffu, ss, o);
    const float inv = 1.f / fmaxf(sqrtf(ss), 1e-12f);
    k0 *= inv; k1 *= inv;
    const float a = abuf[(size_t)token * HH + h];
    const float vv0 = v[base + lane], vv1 = v[base + lane + 32];
    kkout[base + lane]      = k0;
    kkout[base + lane + 32] = k1;
    kvout[base + lane]      = k0 * vv0 * a;
    kvout[base + lane + 32] = k1 * vv1 * a;
}

// ---------------------------------------------------------------------------
// WKV scan: state = state * w_t + kv_t. One block per (b,h), 64 threads.
// ---------------------------------------------------------------------------
__global__ void scan_kernel(const float* __restrict__ kv, const float* __restrict__ wdec,
                            float* __restrict__ wkv) {
    const int bh = blockIdx.x;
    const int b = bh >> 4, h = bh & 15;
    const int d = threadIdx.x;
    const size_t base = (size_t)b * TT * CC + (size_t)h * DD + d;
    const float* kvp = kv + base;
    float* op = wkv + base;
    const float* wp = wdec + (size_t)b * TT * HH + h;
    float state = 0.f;
#pragma unroll 16
    for (int t = 0; t < TT; t++) {
        const float w = wp[(size_t)t * HH];
        const float x = kvp[(size_t)t * CC];
        state = fmaf(state, w, x);
        op[(size_t)t * CC] = state;
    }
}

// ---------------------------------------------------------------------------
// Fused epilogue: bonus + GroupNorm + affine + gate. One warp per (token,h).
// ---------------------------------------------------------------------------
__global__ void epi_kernel(const float* __restrict__ wkv, const float* __restrict__ r,
                           const float* __restrict__ kk, const float* __restrict__ v,
                           const float* __restrict__ r_k, const float* __restrict__ g,
                           const float* __restrict__ lnw, const float* __restrict__ lnb,
                           float* __restrict__ xng) {
    const int gw = (blockIdx.x * blockDim.x + threadIdx.x) >> 5;
    const int lane = threadIdx.x & 31;
    const int token = gw >> 4;
    const int h = gw & 15;
    const size_t base = (size_t)token * CC + h * DD;
    const int c0 = h * DD + lane, c1 = c0 + 32;

    const float s0 = wkv[base + lane],      s1 = wkv[base + lane + 32];
    const float r0 = r[base + lane],        r1 = r[base + lane + 32];
    const float q0 = kk[base + lane],       q1 = kk[base + lane + 32];
    const float v0 = v[base + lane],        v1 = v[base + lane + 32];
    const float g0 = g[base + lane],        g1v = g[base + lane + 32];

    float bsum = r0 * q0 * r_k[c0] + r1 * q1 * r_k[c1];
#pragma unroll
    for (int o = 16; o; o >>= 1) bsum += __shfl_xor_sync(0xffffffffu, bsum, o);

    const float x0 = fmaf(bsum, v0, s0 * r0);
    const float x1 = fmaf(bsum, v1, s1 * r1);

    float ms = x0 + x1;
    float vs = x0 * x0 + x1 * x1;
#pragma unroll
    for (int o = 16; o; o >>= 1) {
        ms += __shfl_xor_sync(0xffffffffu, ms, o);
        vs += __shfl_xor_sync(0xffffffffu, vs, o);
    }
    const float mean = ms * (1.f / 64.f);
    const float var  = vs * (1.f / 64.f) - mean * mean;
    const float rs = rsqrtf(var + 1e-5f);

    xng[base + lane]      = fmaf((x0 - mean) * rs, lnw[c0], lnb[c0]) * g0;
    xng[base + lane + 32] = fmaf((x1 - mean) * rs, lnw[c1], lnb[c1]) * g1v;
}

// ---------------------------------------------------------------------------
// Host launch
// ---------------------------------------------------------------------------
extern "C" void kernel_launch(void* const* d_in, const int* in_sizes, int n_in,
                              void* d_out, int out_size) {
    (void)in_sizes; (void)n_in; (void)out_size;
    const float* x   = (const float*)d_in[0];
    const float* x_r = (const float*)d_in[1];
    const float* x_w = (const float*)d_in[2];
    const float* x_k = (const float*)d_in[3];
    const float* x_v = (const float*)d_in[4];
    const float* x_a = (const float*)d_in[5];
    const float* x_g = (const float*)d_in[6];
    const float* w0  = (const float*)d_in[7];
    const float* w1  = (const float*)d_in[8];
    const float* w2  = (const float*)d_in[9];
    const float* a0  = (const float*)d_in[10];
    const float* a1  = (const float*)d_in[11];
    const float* a2  = (const float*)d_in[12];
    // d_in[13..15] = v0, v1, v2 : mathematically a no-op in the reference
    const float* g1  = (const float*)d_in[16];
    const float* g2  = (const float*)d_in[17];
    const float* k_k = (const float*)d_in[18];
    const float* r_k = (const float*)d_in[19];
    const float* Wr  = (const float*)d_in[20];
    const float* Wk  = (const float*)d_in[21];
    const float* Wv  = (const float*)d_in[22];
    const float* Wo  = (const float*)d_in[23];
    const float* lnw = (const float*)d_in[24];
    const float* lnb = (const float*)d_in[25];
    float* out = (float*)d_out;

    float* scr = nullptr;
    cudaGetSymbolAddress((void**)&scr, g_scr);

    float* rB   = scr + OFF_R;
    float* kB   = scr + OFF_K;      // becomes kk in-place
    float* vB   = scr + OFF_V;
    float* gate = scr + OFF_GATE;   // becomes xng in-place
    float* kvB  = scr + OFF_KV;     // becomes wkv in-place
    float* hw   = scr + OFF_HW;
    float* ha   = scr + OFF_HA;
    float* hg   = scr + OFF_HG;
    float* wd   = scr + OFF_WD;
    float* ab   = scr + OFF_AB;
    float* wt0  = scr + OFF_WT0;
    float* wt1  = scr + OFF_WT1;
    float* wt2  = scr + OFF_WT2;
    float* wt3  = scr + OFF_WT3;

    constexpr int SM128 = (2 * 128 * 36 + 2 * 32 * 136) * 4;   // 71680
    constexpr int SM64  = (2 * 128 * 36 + 2 * 32 * 72) * 4;    // 55296

    cudaFuncSetAttribute(rkv3,
                         cudaFuncAttributeMaxDynamicSharedMemorySize, SM128);
    cudaFuncSetAttribute(lora3,
                         cudaFuncAttributeMaxDynamicSharedMemorySize, SM64);
    cudaFuncSetAttribute(mma_gemm<128, EPI_SIG, false, false>,
                         cudaFuncAttributeMaxDynamicSharedMemorySize, SM128);
    cudaFuncSetAttribute(mma_gemm<128, EPI_NONE, false, true>,
                         cudaFuncAttributeMaxDynamicSharedMemorySize, SM128);

    // 0) pre-round the 4 big weights to tf32 (rna) — one merged launch
    tfround4<<<dim3((CC * CC) / 1024, 4), 256>>>(Wr, Wk, Wv, Wo, wt0, wt1, wt2, wt3);

    // 1) big projections r/k/v merged (fused token-shift mix, B via cp.async)
    rkv3<<<dim3(8, 128, 3), 256, SM128>>>(x, x_r, x_k, x_v, wt0, wt1, wt2, rB, kB, vB);

    // 2) lora stage 1 merged (tanh fused)
    lora3<<<dim3(1, 128, 3), 256, SM64>>>(x, x_w, x_a, x_g, w1, a1, g1, hw, ha, hg);

    // 3) decay + in-context lr
    wa_kernel<<<(BT * HH) / 256, 256>>>(hw, ha, w2, a2, w0, a0, wd, ab);

    // 4) gate stage 2 (sigmoid fused)
    mma_gemm<128, EPI_SIG, false, false><<<dim3(8, 128), 256, SM128>>>(
        hg, nullptr, g2, gate, BT, CC, DLOW);

    // 5) kk normalize + kv  (kk overwrites k in-place)
    kv_kernel<<<(BT * HH) / 8, 256>>>(kB, vB, k_k, ab, kB, kvB);

    // 6) WKV recurrence (wkv overwrites kv in-place)
    scan_kernel<<<8 * HH, 64>>>(kvB, wd, kvB);

    // 7) bonus + GroupNorm + gate (xng overwrites gate in-place)
    epi_kernel<<<(BT * HH) / 8, 256>>>(kvB, rB, kB, vB, r_k, gate, lnw, lnb, gate);

    // 8) output projection (B via cp.async)
    mma_gemm<128, EPI_NONE, false, true><<<dim3(8, 128), 256, SM128>>>(
        gate, nullptr, wt3, out, BT, CC, CC);
}

// round 16
// speedup vs baseline: 1.2978x; 1.0367x over previous
#include <cuda_runtime.h>
#include <math.h>
#include <stdint.h>

// Problem constants
#define BT  16384   // B*T
#define TT  2048    // T
#define CC  1024    // C
#define HH  16      // heads
#define DD  64      // head dim
#define DLOW 64

// ---------------------------------------------------------------------------
// Scratch (aliased lifetimes, ~338 MB)
// ---------------------------------------------------------------------------
#define S_BIG   ((size_t)BT * CC)
#define OFF_R    ((size_t)0)
#define OFF_K    ((size_t)1 * S_BIG)         // aliases KK
#define OFF_V    ((size_t)2 * S_BIG)
#define OFF_GATE ((size_t)3 * S_BIG)         // aliases XNG
#define OFF_KV   ((size_t)4 * S_BIG)         // aliases WKV
#define OFF_HW   ((size_t)5 * S_BIG)
#define OFF_HA   (OFF_HW + (size_t)BT * 64)
#define OFF_HG   (OFF_HA + (size_t)BT * 64)
#define OFF_WD   (OFF_HG + (size_t)BT * 64)
#define OFF_AB   (OFF_WD + (size_t)BT * HH)
#define OFF_WT0  (OFF_AB + (size_t)BT * HH)   // tf32-rounded, TRANSPOSED [N][K]
#define OFF_WT1  (OFF_WT0 + (size_t)CC * CC)
#define OFF_WT2  (OFF_WT1 + (size_t)CC * CC)
#define OFF_WT3  (OFF_WT2 + (size_t)CC * CC)
#define SCR_TOTAL (OFF_WT3 + (size_t)CC * CC)

__device__ float g_scr[SCR_TOTAL];

// ---------------------------------------------------------------------------
// Helpers
// ---------------------------------------------------------------------------
#define EPI_NONE 0
#define EPI_TANH 1
#define EPI_SIG  2

template <int EPI>
__device__ __forceinline__ float epi_apply(float x) {
    if (EPI == EPI_TANH) return tanhf(x);
    if (EPI == EPI_SIG)  return 1.0f / (1.0f + expf(-x));
    return x;
}

__device__ __forceinline__ float to_tf32(float x) {
    uint32_t o;
    asm("cvt.rna.tf32.f32 %0, %1;" : "=r"(o) : "f"(x));
    return __uint_as_float(o);
}

__device__ __forceinline__ void mma_tf32(float* c, const uint32_t* a,
                                         uint32_t b0, uint32_t b1) {
    asm("mma.sync.aligned.m16n8k8.row.col.f32.tf32.tf32.f32 "
        "{%0,%1,%2,%3}, {%4,%5,%6,%7}, {%8,%9}, {%0,%1,%2,%3};"
        : "+f"(c[0]), "+f"(c[1]), "+f"(c[2]), "+f"(c[3])
        : "r"(a[0]), "r"(a[1]), "r"(a[2]), "r"(a[3]), "r"(b0), "r"(b1));
}

#define LDSM_X4(r0, r1, r2, r3, addr) \
    asm volatile("ldmatrix.sync.aligned.m8n8.x4.shared.b16 {%0,%1,%2,%3}, [%4];" \
                 : "=r"(r0), "=r"(r1), "=r"(r2), "=r"(r3) : "r"(addr))
#define LDSM_X2(r0, r1, addr) \
    asm volatile("ldmatrix.sync.aligned.m8n8.x2.shared.b16 {%0,%1}, [%2];" \
                 : "=r"(r0), "=r"(r1) : "r"(addr))

__device__ __forceinline__ uint32_t smem_u32(const void* p) {
    uint32_t a;
    asm("{ .reg .u64 t; cvta.to.shared.u64 t, %1; cvt.u32.u64 %0, t; }"
        : "=r"(a) : "l"(p));
    return a;
}

__device__ __forceinline__ void cp_async16(uint32_t dst, const void* src) {
    asm volatile("cp.async.cg.shared.global [%0], [%1], 16;"
                 :: "r"(dst), "l"(src));
}
#define CP_COMMIT() asm volatile("cp.async.commit_group;")
#define CP_WAIT0()  asm volatile("cp.async.wait_group 0;")

// token-shift mix: a = x + (x - x_prev) * coef  (prev = 0 at t == 0)
template <bool MIX>
__device__ __forceinline__ float4 load_a_frag(const float* __restrict__ A,
                                              const float* __restrict__ coef,
                                              int m, int K, int kidx) {
    float4 cur = *(const float4*)(A + (size_t)m * K + kidx);
    if (MIX) {
        float4 pr = make_float4(0.f, 0.f, 0.f, 0.f);
        if ((m & (TT - 1)) != 0)
            pr = *(const float4*)(A + (size_t)(m - 1) * K + kidx);
        float4 cf = *(const float4*)(coef + kidx);
        cur.x = fmaf(cur.x - pr.x, cf.x, cur.x);
        cur.y = fmaf(cur.y - pr.y, cf.y, cur.y);
        cur.z = fmaf(cur.z - pr.z, cf.z, cur.z);
        cur.w = fmaf(cur.w - pr.w, cf.w, cur.w);
    }
    return cur;
}

// ---------------------------------------------------------------------------
// Pre-pass: WT[n][k] = tf32_rna(W[k][n]) for the 4 big weights (merged).
// ---------------------------------------------------------------------------
__global__ void wtrans4(const float* __restrict__ s0, const float* __restrict__ s1,
                        const float* __restrict__ s2, const float* __restrict__ s3,
                        float* __restrict__ d0, float* __restrict__ d1,
                        float* __restrict__ d2, float* __restrict__ d3) {
    const int z = blockIdx.z;
    const float* W = (z == 0) ? s0 : (z == 1) ? s1 : (z == 2) ? s2 : s3;
    float* WT      = (z == 0) ? d0 : (z == 1) ? d1 : (z == 2) ? d2 : d3;
    __shared__ float t[32][33];
    const int tx = threadIdx.x, ty = threadIdx.y;
    const int bx = blockIdx.x * 32, by = blockIdx.y * 32;
#pragma unroll
    for (int j = 0; j < 32; j += 8)
        t[ty + j][tx] = to_tf32(W[(size_t)(by + ty + j) * CC + bx + tx]);
    __syncthreads();
#pragma unroll
    for (int j = 0; j < 32; j += 8)
        WT[(size_t)(bx + ty + j) * CC + by + tx] = t[tx][ty + j];
}

// ---------------------------------------------------------------------------
// TF32 mma.sync GEMM: C[M,N] = epi(mix(A)[M,K] @ W), 256 threads, BM=128, BK=32.
// A: register-staged (mix fused, rna), fragments via ldmatrix.x4 on As[m][k].
// B when BCP: W given TRANSPOSED [N][K] pre-rounded; cp.async into BsT[n][k],
//   fragments via ldmatrix.x2 (no .trans needed).
// B when !BCP: W [K][N], register-staged into Bs[k][n], scalar fragment LDS.
// __launch_bounds__(256,2) — 2 CTAs/SM.
// ---------------------------------------------------------------------------
template <int BN, int EPI, bool MIX, bool BCP>
__device__ __forceinline__ void
mma_gemm_body(const float* __restrict__ A, const float* __restrict__ coef,
              const float* __restrict__ B, float* __restrict__ C,
              int M, int N, int K) {
    constexpr int BM = 128, BK = 32;
    constexpr int WARPS_N = (BN == 128) ? 4 : 2;
    constexpr int WM = BM / (8 / WARPS_N);
    constexpr int WN = BN / WARPS_N;
    constexpr int MT = WM / 16;
    constexpr int NT = WN / 8;
    constexpr int KS = BK / 8;
    constexpr int ASTR = BK + 4;                       // 36
    constexpr int BSTR = BCP ? (BK + 4) : (BN + 8);    // BsT[n][k] : Bs[k][n]
    constexpr int BBUFE = BCP ? (BN * BSTR) : (BK * BSTR);
    // !BCP staging geometry
    constexpr int BCOL4 = BN / 4;
    constexpr int BKR = 256 / BCOL4;
    constexpr int BQ = BK / BKR;
    // BCP staging geometry: BN rows x 8 chunks(16B) = BN*8 chunks / 256 thr
    constexpr int NCH = (BN * 8) / 256;

    extern __shared__ float sm[];
    float* AsBase = sm;
    float* BsBase = sm + 2 * BM * ASTR;
    const uint32_t as_u32 = smem_u32(AsBase);
    const uint32_t bs_u32 = smem_u32(BsBase);

    const int tid = threadIdx.x;
    const int bm = blockIdx.y, bn = blockIdx.x;
    const int wid = tid >> 5, lane = tid & 31;
    const int lr = lane >> 2, lc = lane & 3;
    const int wM = wid / WARPS_N, wN = wid % WARPS_N;

    const int am = tid >> 1;
    const int ak0 = (tid & 1) * 16;
    const int gm = bm * BM + am;
    const int bkr = tid / BCOL4;
    const int bnc = (tid % BCOL4) * 4;

    // ldmatrix per-lane base offsets (bytes, within one buffer)
    uint32_t aLane[MT];
#pragma unroll
    for (int mt = 0; mt < MT; mt++)
        aLane[mt] = (uint32_t)(((wM * WM + mt * 16 + (lane & 15)) * ASTR
                                + ((lane >> 4) << 2)) * 4);
    uint32_t bLane[NT];
    if (BCP) {
#pragma unroll
        for (int nt = 0; nt < NT; nt++)
            bLane[nt] = (uint32_t)(((wN * WN + nt * 8 + (lane & 7)) * BSTR
                                    + (((lane >> 3) & 1) << 2)) * 4);
    }

    float acc[MT][NT][4];
#pragma unroll
    for (int i = 0; i < MT; i++)
#pragma unroll
        for (int j = 0; j < NT; j++)
#pragma unroll
            for (int q = 0; q < 4; q++) acc[i][j][q] = 0.f;

    const int nk = K / BK;
    float4 aR[4];
    float4 bR[BCP ? 1 : BQ];

    // --- prologue: tile 0 ---
    if (BCP) {
#pragma unroll
        for (int q = 0; q < NCH; q++) {
            const int id = tid * NCH + q;
            const int row = id >> 3, cf = (id & 7) * 4;
            cp_async16(bs_u32 + (uint32_t)((row * BSTR + cf) * 4),
                       B + (size_t)(bn * BN + row) * K + cf);
        }
        CP_COMMIT();
    } else {
#pragma unroll
        for (int q = 0; q < BQ; q++)
            bR[q] = *(const float4*)(B + (size_t)(bkr + q * BKR) * N + bn * BN + bnc);
    }
#pragma unroll
    for (int q = 0; q < 4; q++)
        aR[q] = load_a_frag<MIX>(A, coef, gm, K, ak0 + q * 4);

#pragma unroll
    for (int q = 0; q < 4; q++) {
        float4 t4 = aR[q];
        t4.x = to_tf32(t4.x); t4.y = to_tf32(t4.y);
        t4.z = to_tf32(t4.z); t4.w = to_tf32(t4.w);
        *(float4*)(AsBase + am * ASTR + ak0 + q * 4) = t4;
    }
    if (!BCP) {
#pragma unroll
        for (int q = 0; q < BQ; q++) {
            float4 t4 = bR[q];
            t4.x = to_tf32(t4.x); t4.y = to_tf32(t4.y);
            t4.z = to_tf32(t4.z); t4.w = to_tf32(t4.w);
            *(float4*)(BsBase + (bkr + q * BKR) * BSTR + bnc) = t4;
        }
    }
    if (BCP) CP_WAIT0();
    __syncthreads();

    int cur = 0;
    for (int kt = 0; kt < nk; kt++) {
        if (kt + 1 < nk) {
            const int kb = (kt + 1) * BK;
            if (BCP) {
                const uint32_t bdst = bs_u32 + (uint32_t)((cur ^ 1) * BBUFE * 4);
#pragma unroll
                for (int q = 0; q < NCH; q++) {
                    const int id = tid * NCH + q;
                    const int row = id >> 3, cf = (id & 7) * 4;
                    cp_async16(bdst + (uint32_t)((row * BSTR + cf) * 4),
                               B + (size_t)(bn * BN + row) * K + kb + cf);
                }
                CP_COMMIT();
            } else {
#pragma unroll
                for (int q = 0; q < BQ; q++)
                    bR[q] = *(const float4*)(B + (size_t)(kb + bkr + q * BKR) * N + bn * BN + bnc);
            }
#pragma unroll
            for (int q = 0; q < 4; q++)
                aR[q] = load_a_frag<MIX>(A, coef, gm, K, kb + ak0 + q * 4);
        }

        const uint32_t abase = as_u32 + (uint32_t)(cur * BM * ASTR * 4);
        const uint32_t bbase = bs_u32 + (uint32_t)(cur * BBUFE * 4);
        const float* Bsb = BsBase + cur * BBUFE;

#pragma unroll
        for (int ks = 0; ks < KS; ks++) {
            uint32_t af[MT][4];
            uint32_t bf[NT][2];
#pragma unroll
            for (int mt = 0; mt < MT; mt++)
                LDSM_X4(af[mt][0], af[mt][1], af[mt][2], af[mt][3],
                        abase + aLane[mt] + (uint32_t)(ks * 32));
            if (BCP) {
#pragma unroll
                for (int nt = 0; nt < NT; nt++)
                    LDSM_X2(bf[nt][0], bf[nt][1],
                            bbase + bLane[nt] + (uint32_t)(ks * 32));
            } else {
                const int k0 = ks * 8;
#pragma unroll
                for (int nt = 0; nt < NT; nt++) {
                    const float* bp = Bsb + (k0 + lc) * BSTR + wN * WN + nt * 8 + lr;
                    bf[nt][0] = __float_as_uint(bp[0]);
                    bf[nt][1] = __float_as_uint(bp[4 * BSTR]);
                }
            }
#pragma unroll
            for (int nt = 0; nt < NT; nt++)
#pragma unroll
                for (int mt = 0; mt < MT; mt++)
                    mma_tf32(acc[mt][nt], af[mt], bf[nt][0], bf[nt][1]);
        }

        if (kt + 1 < nk) {
            const int nxt = cur ^ 1;
            float* Asb2 = AsBase + nxt * BM * ASTR;
#pragma unroll
            for (int q = 0; q < 4; q++) {
                float4 t4 = aR[q];
                t4.x = to_tf32(t4.x); t4.y = to_tf32(t4.y);
                t4.z = to_tf32(t4.z); t4.w = to_tf32(t4.w);
                *(float4*)(Asb2 + am * ASTR + ak0 + q * 4) = t4;
            }
            if (!BCP) {
                float* Bsb2 = BsBase + nxt * BBUFE;
#pragma unroll
                for (int q = 0; q < BQ; q++) {
                    float4 t4 = bR[q];
                    t4.x = to_tf32(t4.x); t4.y = to_tf32(t4.y);
                    t4.z = to_tf32(t4.z); t4.w = to_tf32(t4.w);
                    *(float4*)(Bsb2 + (bkr + q * BKR) * BSTR + bnc) = t4;
                }
            }
            if (BCP) CP_WAIT0();
            __syncthreads();
            cur = nxt;
        }
    }

#pragma unroll
    for (int mt = 0; mt < MT; mt++) {
        const int r0 = bm * BM + wM * WM + mt * 16 + lr;
#pragma unroll
        for (int nt = 0; nt < NT; nt++) {
            const int col = bn * BN + wN * WN + nt * 8 + lc * 2;
            float2 o0, o1;
            o0.x = epi_apply<EPI>(acc[mt][nt][0]);
            o0.y = epi_apply<EPI>(acc[mt][nt][1]);
            o1.x = epi_apply<EPI>(acc[mt][nt][2]);
            o1.y = epi_apply<EPI>(acc[mt][nt][3]);
            *(float2*)(C + (size_t)r0 * N + col) = o0;
            *(float2*)(C + (size_t)(r0 + 8) * N + col) = o1;
        }
    }
}

template <int BN, int EPI, bool MIX, bool BCP>
__global__ void __launch_bounds__(256, 2)
mma_gemm(const float* __restrict__ A, const float* __restrict__ coef,
         const float* __restrict__ B, float* __restrict__ C,
         int M, int N, int K) {
    mma_gemm_body<BN, EPI, MIX, BCP>(A, coef, B, C, M, N, K);
}

// merged r/k/v projections: blockIdx.z selects (coef, WT, out); B transposed+cp.async
__global__ void __launch_bounds__(256, 2)
rkv3(const float* __restrict__ x,
     const float* cr, const float* ck, const float* cv,
     const float* Wr, const float* Wk, const float* Wv,
     float* r, float* k, float* v) {
    const int z = blockIdx.z;
    const float* coef = (z == 0) ? cr : (z == 1) ? ck : cv;
    const float* B    = (z == 0) ? Wr : (z == 1) ? Wk : Wv;
    float* C          = (z == 0) ? r  : (z == 1) ? k  : v;
    mma_gemm_body<128, EPI_NONE, true, true>(x, coef, B, C, BT, CC, CC);
}

// merged lora stage-1: blockIdx.z selects (coef, W, out); tanh fused
__global__ void __launch_bounds__(256, 2)
lora3(const float* __restrict__ x,
      const float* cw, const float* ca, const float* cg,
      const float* w1, const float* a1, const float* g1,
      float* hw, float* ha, float* hg) {
    const int z = blockIdx.z;
    const float* coef = (z == 0) ? cw : (z == 1) ? ca : cg;
    const float* B    = (z == 0) ? w1 : (z == 1) ? a1 : g1;
    float* C          = (z == 0) ? hw : (z == 1) ? ha : hg;
    mma_gemm_body<64, EPI_TANH, true, false>(x, coef, B, C, BT, DLOW, CC);
}

// ---------------------------------------------------------------------------
// decay w and in-context lr a:  one thread per (token, head)
// ---------------------------------------------------------------------------
__global__ void wa_kernel(const float* __restrict__ hw, const float* __restrict__ ha,
                          const float* __restrict__ w2, const float* __restrict__ a2,
                          const float* __restrict__ w0, const float* __restrict__ a0,
                          float* __restrict__ wout, float* __restrict__ aout) {
    const int idx = blockIdx.x * blockDim.x + threadIdx.x;
    const int token = idx >> 4;
    const int h = idx & 15;
    const float* hwr = hw + (size_t)token * 64;
    const float* har = ha + (size_t)token * 64;
    float sw = 0.f, sa = 0.f;
#pragma unroll
    for (int kx = 0; kx < 64; kx++) {
        sw = fmaf(hwr[kx], w2[kx * HH + h], sw);
        sa = fmaf(har[kx], a2[kx * HH + h], sa);
    }
    const float zw = w0[h] + sw;
    wout[idx] = 0.60653065971263342f / (1.f + expf(-zw));   // e^{-0.5} * sigmoid
    aout[idx] = 1.f / (1.f + expf(-(a0[h] + sa)));
}

// ---------------------------------------------------------------------------
// kk = normalize((k*k_k) per head), kv = kk * v * a.  One warp per (token,h).
// ---------------------------------------------------------------------------
__global__ void kv_kernel(const float* __restrict__ k, const float* __restrict__ v,
                          const float* __restrict__ k_k, const float* __restrict__ abuf,
                          float* __restrict__ kkout, float* __restrict__ kvout) {
    const int gw = (blockIdx.x * blockDim.x + threadIdx.x) >> 5;
    const int lane = threadIdx.x & 31;
    const int token = gw >> 4;
    const int h = gw & 15;
    const size_t base = (size_t)token * CC + h * DD;
    const int c0 = h * DD + lane, c1 = c0 + 32;

    float k0 = k[base + lane]       * k_k[c0];
    float k1 = k[base + lane + 32]  * k_k[c1];
    float ss = k0 * k0 + k1 * k1;
#pragma unroll
    for (int o = 16; o; o >>= 1) ss += __shfl_xor_sync(0xffffffffu, ss, o);
    const float inv = 1.f / fmaxf(sqrtf(ss), 1e-12f);
    k0 *= inv; k1 *= inv;
    const float a = abuf[(size_t)token * HH + h];
    const float vv0 = v[base + lane], vv1 = v[base + lane + 32];
    kkout[base + lane]      = k0;
    kkout[base + lane + 32] = k1;
    kvout[base + lane]      = k0 * vv0 * a;
    kvout[base + lane + 32] = k1 * vv1 * a;
}

// ---------------------------------------------------------------------------
// WKV scan: state = state * w_t + kv_t. One block per (b,h), 64 threads.
// ---------------------------------------------------------------------------
__global__ void scan_kernel(const float* __restrict__ kv, const float* __restrict__ wdec,
                            float* __restrict__ wkv) {
    const int bh = blockIdx.x;
    const int b = bh >> 4, h = bh & 15;
    const int d = threadIdx.x;
    const size_t base = (size_t)b * TT * CC + (size_t)h * DD + d;
    const float* kvp = kv + base;
    float* op = wkv + base;
    const float* wp = wdec + (size_t)b * TT * HH + h;
    float state = 0.f;
#pragma unroll 16
    for (int t = 0; t < TT; t++) {
        const float w = wp[(size_t)t * HH];
        const float x = kvp[(size_t)t * CC];
        state = fmaf(state, w, x);
        op[(size_t)t * CC] = state;
    }
}

// ---------------------------------------------------------------------------
// Fused epilogue: bonus + GroupNorm + affine + gate. One warp per (token,h).
// ---------------------------------------------------------------------------
__global__ void epi_kernel(const float* __restrict__ wkv, const float* __restrict__ r,
                           const float* __restrict__ kk, const float* __restrict__ v,
                           const float* __restrict__ r_k, const float* __restrict__ g,
                           const float* __restrict__ lnw, const float* __restrict__ lnb,
                           float* __restrict__ xng) {
    const int gw = (blockIdx.x * blockDim.x + threadIdx.x) >> 5;
    const int lane = threadIdx.x & 31;
    const int token = gw >> 4;
    const int h = gw & 15;
    const size_t base = (size_t)token * CC + h * DD;
    const int c0 = h * DD + lane, c1 = c0 + 32;

    const float s0 = wkv[base + lane],      s1 = wkv[base + lane + 32];
    const float r0 = r[base + lane],        r1 = r[base + lane + 32];
    const float q0 = kk[base + lane],       q1 = kk[base + lane + 32];
    const float v0 = v[base + lane],        v1 = v[base + lane + 32];
    const float g0 = g[base + lane],        g1v = g[base + lane + 32];

    float bsum = r0 * q0 * r_k[c0] + r1 * q1 * r_k[c1];
#pragma unroll
    for (int o = 16; o; o >>= 1) bsum += __shfl_xor_sync(0xffffffffu, bsum, o);

    const float x0 = fmaf(bsum, v0, s0 * r0);
    const float x1 = fmaf(bsum, v1, s1 * r1);

    float ms = x0 + x1;
    float vs = x0 * x0 + x1 * x1;
#pragma unroll
    for (int o = 16; o; o >>= 1) {
        ms += __shfl_xor_sync(0xffffffffu, ms, o);
        vs += __shfl_xor_sync(0xffffffffu, vs, o);
    }
    const float mean = ms * (1.f / 64.f);
    const float var  = vs * (1.f / 64.f) - mean * mean;
    const float rs = rsqrtf(var + 1e-5f);

    xng[base + lane]      = fmaf((x0 - mean) * rs, lnw[c0], lnb[c0]) * g0;
    xng[base + lane + 32] = fmaf((x1 - mean) * rs, lnw[c1], lnb[c1]) * g1v;
}

// ---------------------------------------------------------------------------
// Host launch
// ---------------------------------------------------------------------------
extern "C" void kernel_launch(void* const* d_in, const int* in_sizes, int n_in,
                              void* d_out, int out_size) {
    (void)in_sizes; (void)n_in; (void)out_size;
    const float* x   = (const float*)d_in[0];
    const float* x_r = (const float*)d_in[1];
    const float* x_w = (const float*)d_in[2];
    const float* x_k = (const float*)d_in[3];
    const float* x_v = (const float*)d_in[4];
    const float* x_a = (const float*)d_in[5];
    const float* x_g = (const float*)d_in[6];
    const float* w0  = (const float*)d_in[7];
    const float* w1  = (const float*)d_in[8];
    const float* w2  = (const float*)d_in[9];
    const float* a0  = (const float*)d_in[10];
    const float* a1  = (const float*)d_in[11];
    const float* a2  = (const float*)d_in[12];
    // d_in[13..15] = v0, v1, v2 : mathematically a no-op in the reference
    const float* g1  = (const float*)d_in[16];
    const float* g2  = (const float*)d_in[17];
    const float* k_k = (const float*)d_in[18];
    const float* r_k = (const float*)d_in[19];
    const float* Wr  = (const float*)d_in[20];
    const float* Wk  = (const float*)d_in[21];
    const float* Wv  = (const float*)d_in[22];
    const float* Wo  = (const float*)d_in[23];
    const float* lnw = (const float*)d_in[24];
    const float* lnb = (const float*)d_in[25];
    float* out = (float*)d_out;

    float* scr = nullptr;
    cudaGetSymbolAddress((void**)&scr, g_scr);

    float* rB   = scr + OFF_R;
    float* kB   = scr + OFF_K;      // becomes kk in-place
    float* vB   = scr + OFF_V;
    float* gate = scr + OFF_GATE;   // becomes xng in-place
    float* kvB  = scr + OFF_KV;     // becomes wkv in-place
    float* hw   = scr + OFF_HW;
    float* ha   = scr + OFF_HA;
    float* hg   = scr + OFF_HG;
    float* wd   = scr + OFF_WD;
    float* ab   = scr + OFF_AB;
    float* wt0  = scr + OFF_WT0;
    float* wt1  = scr + OFF_WT1;
    float* wt2  = scr + OFF_WT2;
    float* wt3  = scr + OFF_WT3;

    constexpr int SMTCP = (2 * 128 * 36 + 2 * 128 * 36) * 4;   // 73728 (BCP, BN=128)
    constexpr int SM128 = (2 * 128 * 36 + 2 * 32 * 136) * 4;   // 71680 (!BCP, BN=128)
    constexpr int SM64  = (2 * 128 * 36 + 2 * 32 * 72) * 4;    // 55296 (!BCP, BN=64)

    cudaFuncSetAttribute(rkv3,
                         cudaFuncAttributeMaxDynamicSharedMemorySize, SMTCP);
    cudaFuncSetAttribute(lora3,
                         cudaFuncAttributeMaxDynamicSharedMemorySize, SM64);
    cudaFuncSetAttribute(mma_gemm<128, EPI_SIG, false, false>,
                         cudaFuncAttributeMaxDynamicSharedMemorySize, SM128);
    cudaFuncSetAttribute(mma_gemm<128, EPI_NONE, false, true>,
                         cudaFuncAttributeMaxDynamicSharedMemorySize, SMTCP);

    // 0) pre-round + transpose the 4 big weights (one merged launch)
    wtrans4<<<dim3(32, 32, 4), dim3(32, 8)>>>(Wr, Wk, Wv, Wo, wt0, wt1, wt2, wt3);

    // 1) big projections r/k/v merged (mix fused; B transposed via cp.async+ldmatrix)
    rkv3<<<dim3(8, 128, 3), 256, SMTCP>>>(x, x_r, x_k, x_v, wt0, wt1, wt2, rB, kB, vB);

    // 2) lora stage 1 merged (tanh fused)
    lora3<<<dim3(1, 128, 3), 256, SM64>>>(x, x_w, x_a, x_g, w1, a1, g1, hw, ha, hg);

    // 3) decay + in-context lr
    wa_kernel<<<(BT * HH) / 256, 256>>>(hw, ha, w2, a2, w0, a0, wd, ab);

    // 4) gate stage 2 (sigmoid fused)
    mma_gemm<128, EPI_SIG, false, false><<<dim3(8, 128), 256, SM128>>>(
        hg, nullptr, g2, gate, BT, CC, DLOW);

    // 5) kk normalize + kv  (kk overwrites k in-place)
    kv_kernel<<<(BT * HH) / 8, 256>>>(kB, vB, k_k, ab, kB, kvB);

    // 6) WKV recurrence (wkv overwrites kv in-place)
    scan_kernel<<<8 * HH, 64>>>(kvB, wd, kvB);

    // 7) bonus + GroupNorm + gate (xng overwrites gate in-place)
    epi_kernel<<<(BT * HH) / 8, 256>>>(kvB, rB, kB, vB, r_k, gate, lnw, lnb, gate);

    // 8) output projection (B transposed via cp.async+ldmatrix)
    mma_gemm<128, EPI_NONE, false, true><<<dim3(8, 128), 256, SMTCP>>>(
        gate, nullptr, wt3, out, BT, CC, CC);
}

// round 17
// speedup vs baseline: 1.3136x; 1.0122x over previous
#include <cuda_runtime.h>
#include <math.h>
#include <stdint.h>

// Problem constants
#define BT  16384   // B*T
#define TT  2048    // T
#define CC  1024    // C
#define HH  16      // heads
#define DD  64      // head dim
#define DLOW 64

// ---------------------------------------------------------------------------
// Scratch (aliased lifetimes, ~338 MB)
// ---------------------------------------------------------------------------
#define S_BIG   ((size_t)BT * CC)
#define OFF_R    ((size_t)0)
#define OFF_K    ((size_t)1 * S_BIG)         // aliases KK
#define OFF_V    ((size_t)2 * S_BIG)
#define OFF_GATE ((size_t)3 * S_BIG)         // aliases XNG
#define OFF_KV   ((size_t)4 * S_BIG)         // aliases WKV
#define OFF_HW   ((size_t)5 * S_BIG)
#define OFF_HA   (OFF_HW + (size_t)BT * 64)
#define OFF_HG   (OFF_HA + (size_t)BT * 64)
#define OFF_WD   (OFF_HG + (size_t)BT * 64)
#define OFF_AB   (OFF_WD + (size_t)BT * HH)
#define OFF_WT0  (OFF_AB + (size_t)BT * HH)   // tf32-rounded, TRANSPOSED [N][K]
#define OFF_WT1  (OFF_WT0 + (size_t)CC * CC)
#define OFF_WT2  (OFF_WT1 + (size_t)CC * CC)
#define OFF_WT3  (OFF_WT2 + (size_t)CC * CC)
#define SCR_TOTAL (OFF_WT3 + (size_t)CC * CC)

__device__ float g_scr[SCR_TOTAL];

// ---------------------------------------------------------------------------
// Helpers
// ---------------------------------------------------------------------------
#define EPI_NONE 0
#define EPI_TANH 1
#define EPI_SIG  2

template <int EPI>
__device__ __forceinline__ float epi_apply(float x) {
    if (EPI == EPI_TANH) return tanhf(x);
    if (EPI == EPI_SIG)  return 1.0f / (1.0f + expf(-x));
    return x;
}

__device__ __forceinline__ float to_tf32(float x) {
    uint32_t o;
    asm("cvt.rna.tf32.f32 %0, %1;" : "=r"(o) : "f"(x));
    return __uint_as_float(o);
}

__device__ __forceinline__ void mma_tf32(float* c, const uint32_t* a,
                                         uint32_t b0, uint32_t b1) {
    asm("mma.sync.aligned.m16n8k8.row.col.f32.tf32.tf32.f32 "
        "{%0,%1,%2,%3}, {%4,%5,%6,%7}, {%8,%9}, {%0,%1,%2,%3};"
        : "+f"(c[0]), "+f"(c[1]), "+f"(c[2]), "+f"(c[3])
        : "r"(a[0]), "r"(a[1]), "r"(a[2]), "r"(a[3]), "r"(b0), "r"(b1));
}

#define LDSM_X4(r0, r1, r2, r3, addr) \
    asm volatile("ldmatrix.sync.aligned.m8n8.x4.shared.b16 {%0,%1,%2,%3}, [%4];" \
                 : "=r"(r0), "=r"(r1), "=r"(r2), "=r"(r3) : "r"(addr))

__device__ __forceinline__ uint32_t smem_u32(const void* p) {
    uint32_t a;
    asm("{ .reg .u64 t; cvta.to.shared.u64 t, %1; cvt.u32.u64 %0, t; }"
        : "=r"(a) : "l"(p));
    return a;
}

__device__ __forceinline__ void cp_async16(uint32_t dst, const void* src) {
    asm volatile("cp.async.cg.shared.global [%0], [%1], 16;"
                 :: "r"(dst), "l"(src));
}
#define CP_COMMIT() asm volatile("cp.async.commit_group;")
#define CP_WAIT0()  asm volatile("cp.async.wait_group 0;")

// token-shift mix: a = x + (x - x_prev) * coef  (prev = 0 at t == 0)
template <bool MIX>
__device__ __forceinline__ float4 load_a_frag(const float* __restrict__ A,
                                              const float* __restrict__ coef,
                                              int m, int K, int kidx) {
    float4 cur = *(const float4*)(A + (size_t)m * K + kidx);
    if (MIX) {
        float4 pr = make_float4(0.f, 0.f, 0.f, 0.f);
        if ((m & (TT - 1)) != 0)
            pr = *(const float4*)(A + (size_t)(m - 1) * K + kidx);
        float4 cf = *(const float4*)(coef + kidx);
        cur.x = fmaf(cur.x - pr.x, cf.x, cur.x);
        cur.y = fmaf(cur.y - pr.y, cf.y, cur.y);
        cur.z = fmaf(cur.z - pr.z, cf.z, cur.z);
        cur.w = fmaf(cur.w - pr.w, cf.w, cur.w);
    }
    return cur;
}

// ---------------------------------------------------------------------------
// Pre-pass: WT[n][k] = tf32_rna(W[k][n]) for the 4 big weights (merged).
// ---------------------------------------------------------------------------
__global__ void wtrans4(const float* __restrict__ s0, const float* __restrict__ s1,
                        const float* __restrict__ s2, const float* __restrict__ s3,
                        float* __restrict__ d0, float* __restrict__ d1,
                        float* __restrict__ d2, float* __restrict__ d3) {
    const int z = blockIdx.z;
    const float* W = (z == 0) ? s0 : (z == 1) ? s1 : (z == 2) ? s2 : s3;
    float* WT      = (z == 0) ? d0 : (z == 1) ? d1 : (z == 2) ? d2 : d3;
    __shared__ float t[32][33];
    const int tx = threadIdx.x, ty = threadIdx.y;
    const int bx = blockIdx.x * 32, by = blockIdx.y * 32;
#pragma unroll
    for (int j = 0; j < 32; j += 8)
        t[ty + j][tx] = to_tf32(W[(size_t)(by + ty + j) * CC + bx + tx]);
    __syncthreads();
#pragma unroll
    for (int j = 0; j < 32; j += 8)
        WT[(size_t)(bx + ty + j) * CC + by + tx] = t[tx][ty + j];
}

// ---------------------------------------------------------------------------
// TF32 mma.sync GEMM: C[M,N] = epi(mix(A)[M,K] @ W), 256 threads, BM=128, BK=32.
// A when !ACP: register-staged (mix fused, rna), ldmatrix.x4 fragments.
// A when ACP:  A is pre-rounded tf32 in gmem -> cp.async into As[m][k].
// B when BCP: W TRANSPOSED [N][K] pre-rounded; cp.async into BsT[n][k],
//   fragments via paired ldmatrix.x4 (2 nt-groups per load).
// B when !BCP: W [K][N], register-staged into Bs[k][n], scalar fragment LDS.
// __launch_bounds__(256,2) — 2 CTAs/SM.
// ---------------------------------------------------------------------------
template <int BN, int EPI, bool MIX, bool BCP, bool ACP>
__device__ __forceinline__ void
mma_gemm_body(const float* __restrict__ A, const float* __restrict__ coef,
              const float* __restrict__ B, float* __restrict__ C,
              int M, int N, int K) {
    constexpr int BM = 128, BK = 32;
    constexpr int WARPS_N = (BN == 128) ? 4 : 2;
    constexpr int WM = BM / (8 / WARPS_N);
    constexpr int WN = BN / WARPS_N;
    constexpr int MT = WM / 16;
    constexpr int NT = WN / 8;
    constexpr int KS = BK / 8;
    constexpr int ASTR = BK + 4;                       // 36
    constexpr int BSTR = BCP ? (BK + 4) : (BN + 8);    // BsT[n][k] : Bs[k][n]
    constexpr int BBUFE = BCP ? (BN * BSTR) : (BK * BSTR);
    // !BCP staging geometry
    constexpr int BCOL4 = BN / 4;
    constexpr int BKR = 256 / BCOL4;
    constexpr int BQ = BK / BKR;
    // cp.async staging: rows x 8 chunks(16B) / 256 thr
    constexpr int NCH = (BN * 8) / 256;
    constexpr int ACH = (BM * 8) / 256;                // 4

    extern __shared__ float sm[];
    float* AsBase = sm;
    float* BsBase = sm + 2 * BM * ASTR;
    const uint32_t as_u32 = smem_u32(AsBase);
    const uint32_t bs_u32 = smem_u32(BsBase);

    const int tid = threadIdx.x;
    const int bm = blockIdx.y, bn = blockIdx.x;
    const int wid = tid >> 5, lane = tid & 31;
    const int lr = lane >> 2, lc = lane & 3;
    const int wM = wid / WARPS_N, wN = wid % WARPS_N;

    const int am = tid >> 1;
    const int ak0 = (tid & 1) * 16;
    const int gm = bm * BM + am;
    const int bkr = tid / BCOL4;
    const int bnc = (tid % BCOL4) * 4;

    // ldmatrix per-lane base offsets (bytes, within one buffer)
    uint32_t aLane[MT];
#pragma unroll
    for (int mt = 0; mt < MT; mt++)
        aLane[mt] = (uint32_t)(((wM * WM + mt * 16 + (lane & 15)) * ASTR
                                + ((lane >> 4) << 2)) * 4);
    // paired B x4: matrices {p*16+(0..7) rows, k 0|4} and {p*16+8.. rows, k 0|4}
    uint32_t bLane4[(NT > 1) ? NT / 2 : 1];
    if (BCP) {
#pragma unroll
        for (int p = 0; p < NT / 2; p++)
            bLane4[p] = (uint32_t)(((wN * WN + p * 16 + (lane & 7) + ((lane >> 4) << 3)) * BSTR
                                    + (((lane >> 3) & 1) << 2)) * 4);
    }

    float acc[MT][NT][4];
#pragma unroll
    for (int i = 0; i < MT; i++)
#pragma unroll
        for (int j = 0; j < NT; j++)
#pragma unroll
            for (int q = 0; q < 4; q++) acc[i][j][q] = 0.f;

    const int nk = K / BK;
    float4 aR[ACP ? 1 : 4];
    float4 bR[BCP ? 1 : BQ];

    // --- prologue: tile 0 ---
    if (BCP) {
#pragma unroll
        for (int q = 0; q < NCH; q++) {
            const int id = tid * NCH + q;
            const int row = id >> 3, cf = (id & 7) * 4;
            cp_async16(bs_u32 + (uint32_t)((row * BSTR + cf) * 4),
                       B + (size_t)(bn * BN + row) * K + cf);
        }
    } else {
#pragma unroll
        for (int q = 0; q < BQ; q++)
            bR[q] = *(const float4*)(B + (size_t)(bkr + q * BKR) * N + bn * BN + bnc);
    }
    if (ACP) {
#pragma unroll
        for (int q = 0; q < ACH; q++) {
            const int id = tid * ACH + q;
            const int row = id >> 3, cf = (id & 7) * 4;
            cp_async16(as_u32 + (uint32_t)((row * ASTR + cf) * 4),
                       A + (size_t)(bm * BM + row) * K + cf);
        }
    } else {
#pragma unroll
        for (int q = 0; q < 4; q++)
            aR[q] = load_a_frag<MIX>(A, coef, gm, K, ak0 + q * 4);
#pragma unroll
        for (int q = 0; q < 4; q++) {
            float4 t4 = aR[q];
            t4.x = to_tf32(t4.x); t4.y = to_tf32(t4.y);
            t4.z = to_tf32(t4.z); t4.w = to_tf32(t4.w);
            *(float4*)(AsBase + am * ASTR + ak0 + q * 4) = t4;
        }
    }
    if (!BCP) {
#pragma unroll
        for (int q = 0; q < BQ; q++) {
            float4 t4 = bR[q];
            t4.x = to_tf32(t4.x); t4.y = to_tf32(t4.y);
            t4.z = to_tf32(t4.z); t4.w = to_tf32(t4.w);
            *(float4*)(BsBase + (bkr + q * BKR) * BSTR + bnc) = t4;
        }
    }
    if (BCP || ACP) { CP_COMMIT(); CP_WAIT0(); }
    __syncthreads();

    int cur = 0;
    for (int kt = 0; kt < nk; kt++) {
        if (kt + 1 < nk) {
            const int kb = (kt + 1) * BK;
            if (BCP) {
                const uint32_t bdst = bs_u32 + (uint32_t)((cur ^ 1) * BBUFE * 4);
#pragma unroll
                for (int q = 0; q < NCH; q++) {
                    const int id = tid * NCH + q;
                    const int row = id >> 3, cf = (id & 7) * 4;
                    cp_async16(bdst + (uint32_t)((row * BSTR + cf) * 4),
                               B + (size_t)(bn * BN + row) * K + kb + cf);
                }
            } else {
#pragma unroll
                for (int q = 0; q < BQ; q++)
                    bR[q] = *(const float4*)(B + (size_t)(kb + bkr + q * BKR) * N + bn * BN + bnc);
            }
            if (ACP) {
                const uint32_t adst = as_u32 + (uint32_t)((cur ^ 1) * BM * ASTR * 4);
#pragma unroll
                for (int q = 0; q < ACH; q++) {
                    const int id = tid * ACH + q;
                    const int row = id >> 3, cf = (id & 7) * 4;
                    cp_async16(adst + (uint32_t)((row * ASTR + cf) * 4),
                               A + (size_t)(bm * BM + row) * K + kb + cf);
                }
            } else {
#pragma unroll
                for (int q = 0; q < 4; q++)
                    aR[q] = load_a_frag<MIX>(A, coef, gm, K, kb + ak0 + q * 4);
            }
            if (BCP || ACP) CP_COMMIT();
        }

        const uint32_t abase = as_u32 + (uint32_t)(cur * BM * ASTR * 4);
        const uint32_t bbase = bs_u32 + (uint32_t)(cur * BBUFE * 4);
        const float* Bsb = BsBase + cur * BBUFE;

#pragma unroll
        for (int ks = 0; ks < KS; ks++) {
            uint32_t af[MT][4];
            uint32_t bf[NT][2];
#pragma unroll
            for (int mt = 0; mt < MT; mt++)
                LDSM_X4(af[mt][0], af[mt][1], af[mt][2], af[mt][3],
                        abase + aLane[mt] + (uint32_t)(ks * 32));
            if (BCP) {
#pragma unroll
                for (int p = 0; p < NT / 2; p++)
                    LDSM_X4(bf[2 * p][0], bf[2 * p][1], bf[2 * p + 1][0], bf[2 * p + 1][1],
                            bbase + bLane4[p] + (uint32_t)(ks * 32));
            } else {
                const int k0 = ks * 8;
#pragma unroll
                for (int nt = 0; nt < NT; nt++) {
                    const float* bp = Bsb + (k0 + lc) * BSTR + wN * WN + nt * 8 + lr;
                    bf[nt][0] = __float_as_uint(bp[0]);
                    bf[nt][1] = __float_as_uint(bp[4 * BSTR]);
                }
            }
#pragma unroll
            for (int nt = 0; nt < NT; nt++)
#pragma unroll
                for (int mt = 0; mt < MT; mt++)
                    mma_tf32(acc[mt][nt], af[mt], bf[nt][0], bf[nt][1]);
        }

        if (kt + 1 < nk) {
            const int nxt = cur ^ 1;
            if (!ACP) {
                float* Asb2 = AsBase + nxt * BM * ASTR;
#pragma unroll
                for (int q = 0; q < 4; q++) {
                    float4 t4 = aR[q];
                    t4.x = to_tf32(t4.x); t4.y = to_tf32(t4.y);
                    t4.z = to_tf32(t4.z); t4.w = to_tf32(t4.w);
                    *(float4*)(Asb2 + am * ASTR + ak0 + q * 4) = t4;
                }
            }
            if (!BCP) {
                float* Bsb2 = BsBase + nxt * BBUFE;
#pragma unroll
                for (int q = 0; q < BQ; q++) {
                    float4 t4 = bR[q];
                    t4.x = to_tf32(t4.x); t4.y = to_tf32(t4.y);
                    t4.z = to_tf32(t4.z); t4.w = to_tf32(t4.w);
                    *(float4*)(Bsb2 + (bkr + q * BKR) * BSTR + bnc) = t4;
                }
            }
            if (BCP || ACP) CP_WAIT0();
            __syncthreads();
            cur = nxt;
        }
    }

#pragma unroll
    for (int mt = 0; mt < MT; mt++) {
        const int r0 = bm * BM + wM * WM + mt * 16 + lr;
#pragma unroll
        for (int nt = 0; nt < NT; nt++) {
            const int col = bn * BN + wN * WN + nt * 8 + lc * 2;
            float2 o0, o1;
            o0.x = epi_apply<EPI>(acc[mt][nt][0]);
            o0.y = epi_apply<EPI>(acc[mt][nt][1]);
            o1.x = epi_apply<EPI>(acc[mt][nt][2]);
            o1.y = epi_apply<EPI>(acc[mt][nt][3]);
            *(float2*)(C + (size_t)r0 * N + col) = o0;
            *(float2*)(C + (size_t)(r0 + 8) * N + col) = o1;
        }
    }
}

template <int BN, int EPI, bool MIX, bool BCP, bool ACP>
__global__ void __launch_bounds__(256, 2)
mma_gemm(const float* __restrict__ A, const float* __restrict__ coef,
         const float* __restrict__ B, float* __restrict__ C,
         int M, int N, int K) {
    mma_gemm_body<BN, EPI, MIX, BCP, ACP>(A, coef, B, C, M, N, K);
}

// merged r/k/v projections: blockIdx.z selects (coef, WT, out)
__global__ void __launch_bounds__(256, 2)
rkv3(const float* __restrict__ x,
     const float* cr, const float* ck, const float* cv,
     const float* Wr, const float* Wk, const float* Wv,
     float* r, float* k, float* v) {
    const int z = blockIdx.z;
    const float* coef = (z == 0) ? cr : (z == 1) ? ck : cv;
    const float* B    = (z == 0) ? Wr : (z == 1) ? Wk : Wv;
    float* C          = (z == 0) ? r  : (z == 1) ? k  : v;
    mma_gemm_body<128, EPI_NONE, true, true, false>(x, coef, B, C, BT, CC, CC);
}

// merged lora stage-1: blockIdx.z selects (coef, W, out); tanh fused
__global__ void __launch_bounds__(256, 2)
lora3(const float* __restrict__ x,
      const float* cw, const float* ca, const float* cg,
      const float* w1, const float* a1, const float* g1,
      float* hw, float* ha, float* hg) {
    const int z = blockIdx.z;
    const float* coef = (z == 0) ? cw : (z == 1) ? ca : cg;
    const float* B    = (z == 0) ? w1 : (z == 1) ? a1 : g1;
    float* C          = (z == 0) ? hw : (z == 1) ? ha : hg;
    mma_gemm_body<64, EPI_TANH, true, false, false>(x, coef, B, C, BT, DLOW, CC);
}

// ---------------------------------------------------------------------------
// decay w and in-context lr a:  one thread per (token, head)
// ---------------------------------------------------------------------------
__global__ void wa_kernel(const float* __restrict__ hw, const float* __restrict__ ha,
                          const float* __restrict__ w2, const float* __restrict__ a2,
                          const float* __restrict__ w0, const float* __restrict__ a0,
                          float* __restrict__ wout, float* __restrict__ aout) {
    const int idx = blockIdx.x * blockDim.x + threadIdx.x;
    const int token = idx >> 4;
    const int h = idx & 15;
    const float* hwr = hw + (size_t)token * 64;
    const float* har = ha + (size_t)token * 64;
    float sw = 0.f, sa = 0.f;
#pragma unroll
    for (int kx = 0; kx < 64; kx++) {
        sw = fmaf(hwr[kx], w2[kx * HH + h], sw);
        sa = fmaf(har[kx], a2[kx * HH + h], sa);
    }
    const float zw = w0[h] + sw;
    wout[idx] = 0.60653065971263342f / (1.f + expf(-zw));   // e^{-0.5} * sigmoid
    aout[idx] = 1.f / (1.f + expf(-(a0[h] + sa)));
}

// ---------------------------------------------------------------------------
// kk = normalize((k*k_k) per head), kv = kk * v * a.  One warp per (token,h).
// ---------------------------------------------------------------------------
__global__ void kv_kernel(const float* __restrict__ k, const float* __restrict__ v,
                          const float* __restrict__ k_k, const float* __restrict__ abuf,
                          float* __restrict__ kkout, float* __restrict__ kvout) {
    const int gw = (blockIdx.x * blockDim.x + threadIdx.x) >> 5;
    const int lane = threadIdx.x & 31;
    const int token = gw >> 4;
    const int h = gw & 15;
    const size_t base = (size_t)token * CC + h * DD;
    const int c0 = h * DD + lane, c1 = c0 + 32;

    float k0 = k[base + lane]       * k_k[c0];
    float k1 = k[base + lane + 32]  * k_k[c1];
    float ss = k0 * k0 + k1 * k1;
#pragma unroll
    for (int o = 16; o; o >>= 1) ss += __shfl_xor_sync(0xffffffffu, ss, o);
    const float inv = 1.f / fmaxf(sqrtf(ss), 1e-12f);
    k0 *= inv; k1 *= inv;
    const float a = abuf[(size_t)token * HH + h];
    const float vv0 = v[base + lane], vv1 = v[base + lane + 32];
    kkout[base + lane]      = k0;
    kkout[base + lane + 32] = k1;
    kvout[base + lane]      = k0 * vv0 * a;
    kvout[base + lane + 32] = k1 * vv1 * a;
}

// ---------------------------------------------------------------------------
// WKV scan: state = state * w_t + kv_t. One block per (b,h), 64 threads.
// ---------------------------------------------------------------------------
__global__ void scan_kernel(const float* __restrict__ kv, const float* __restrict__ wdec,
                            float* __restrict__ wkv) {
    const int bh = blockIdx.x;
    const int b = bh >> 4, h = bh & 15;
    const int d = threadIdx.x;
    const size_t base = (size_t)b * TT * CC + (size_t)h * DD + d;
    const float* kvp = kv + base;
    float* op = wkv + base;
    const float* wp = wdec + (size_t)b * TT * HH + h;
    float state = 0.f;
#pragma unroll 16
    for (int t = 0; t < TT; t++) {
        const float w = wp[(size_t)t * HH];
        const float x = kvp[(size_t)t * CC];
        state = fmaf(state, w, x);
        op[(size_t)t * CC] = state;
    }
}

// ---------------------------------------------------------------------------
// Fused epilogue: bonus + GroupNorm + affine + gate. One warp per (token,h).
// Output pre-rounded to tf32 (rna) so the out-projection can cp.async its A —
// bit-identical to rounding inside the GEMM staging.
// ---------------------------------------------------------------------------
__global__ void epi_kernel(const float* __restrict__ wkv, const float* __restrict__ r,
                           const float* __restrict__ kk, const float* __restrict__ v,
                           const float* __restrict__ r_k, const float* __restrict__ g,
                           const float* __restrict__ lnw, const float* __restrict__ lnb,
                           float* __restrict__ xng) {
    const int gw = (blockIdx.x * blockDim.x + threadIdx.x) >> 5;
    const int lane = threadIdx.x & 31;
    const int token = gw >> 4;
    const int h = gw & 15;
    const size_t base = (size_t)token * CC + h * DD;
    const int c0 = h * DD + lane, c1 = c0 + 32;

    const float s0 = wkv[base + lane],      s1 = wkv[base + lane + 32];
    const float r0 = r[base + lane],        r1 = r[base + lane + 32];
    const float q0 = kk[base + lane],       q1 = kk[base + lane + 32];
    const float v0 = v[base + lane],        v1 = v[base + lane + 32];
    const float g0 = g[base + lane],        g1v = g[base + lane + 32];

    float bsum = r0 * q0 * r_k[c0] + r1 * q1 * r_k[c1];
#pragma unroll
    for (int o = 16; o; o >>= 1) bsum += __shfl_xor_sync(0xffffffffu, bsum, o);

    const float x0 = fmaf(bsum, v0, s0 * r0);
    const float x1 = fmaf(bsum, v1, s1 * r1);

    float ms = x0 + x1;
    float vs = x0 * x0 + x1 * x1;
#pragma unroll
    for (int o = 16; o; o >>= 1) {
        ms += __shfl_xor_sync(0xffffffffu, ms, o);
        vs += __shfl_xor_sync(0xffffffffu, vs, o);
    }
    const float mean = ms * (1.f / 64.f);
    const float var  = vs * (1.f / 64.f) - mean * mean;
    const float rs = rsqrtf(var + 1e-5f);

    xng[base + lane]      = to_tf32(fmaf((x0 - mean) * rs, lnw[c0], lnb[c0]) * g0);
    xng[base + lane + 32] = to_tf32(fmaf((x1 - mean) * rs, lnw[c1], lnb[c1]) * g1v);
}

// ---------------------------------------------------------------------------
// Host launch
// ---------------------------------------------------------------------------
extern "C" void kernel_launch(void* const* d_in, const int* in_sizes, int n_in,
                              void* d_out, int out_size) {
    (void)in_sizes; (void)n_in; (void)out_size;
    const float* x   = (const float*)d_in[0];
    const float* x_r = (const float*)d_in[1];
    const float* x_w = (const float*)d_in[2];
    const float* x_k = (const float*)d_in[3];
    const float* x_v = (const float*)d_in[4];
    const float* x_a = (const float*)d_in[5];
    const float* x_g = (const float*)d_in[6];
    const float* w0  = (const float*)d_in[7];
    const float* w1  = (const float*)d_in[8];
    const float* w2  = (const float*)d_in[9];
    const float* a0  = (const float*)d_in[10];
    const float* a1  = (const float*)d_in[11];
    const float* a2  = (const float*)d_in[12];
    // d_in[13..15] = v0, v1, v2 : mathematically a no-op in the reference
    const float* g1  = (const float*)d_in[16];
    const float* g2  = (const float*)d_in[17];
    const float* k_k = (const float*)d_in[18];
    const float* r_k = (const float*)d_in[19];
    const float* Wr  = (const float*)d_in[20];
    const float* Wk  = (const float*)d_in[21];
    const float* Wv  = (const float*)d_in[22];
    const float* Wo  = (const float*)d_in[23];
    const float* lnw = (const float*)d_in[24];
    const float* lnb = (const float*)d_in[25];
    float* out = (float*)d_out;

    float* scr = nullptr;
    cudaGetSymbolAddress((void**)&scr, g_scr);

    float* rB   = scr + OFF_R;
    float* kB   = scr + OFF_K;      // becomes kk in-place
    float* vB   = scr + OFF_V;
    float* gate = scr + OFF_GATE;   // becomes xng in-place (tf32-rounded)
    float* kvB  = scr + OFF_KV;     // becomes wkv in-place
    float* hw   = scr + OFF_HW;
    float* ha   = scr + OFF_HA;
    float* hg   = scr + OFF_HG;
    float* wd   = scr + OFF_WD;
    float* ab   = scr + OFF_AB;
    float* wt0  = scr + OFF_WT0;
    float* wt1  = scr + OFF_WT1;
    float* wt2  = scr + OFF_WT2;
    float* wt3  = scr + OFF_WT3;

    constexpr int SMTCP = (2 * 128 * 36 + 2 * 128 * 36) * 4;   // 73728 (BCP, BN=128)
    constexpr int SM128 = (2 * 128 * 36 + 2 * 32 * 136) * 4;   // 71680 (!BCP, BN=128)
    constexpr int SM64  = (2 * 128 * 36 + 2 * 32 * 72) * 4;    // 55296 (!BCP, BN=64)

    cudaFuncSetAttribute(rkv3,
                         cudaFuncAttributeMaxDynamicSharedMemorySize, SMTCP);
    cudaFuncSetAttribute(lora3,
                         cudaFuncAttributeMaxDynamicSharedMemorySize, SM64);
    cudaFuncSetAttribute(mma_gemm<128, EPI_SIG, false, false, false>,
                         cudaFuncAttributeMaxDynamicSharedMemorySize, SM128);
    cudaFuncSetAttribute(mma_gemm<128, EPI_NONE, false, true, true>,
                         cudaFuncAttributeMaxDynamicSharedMemorySize, SMTCP);

    // 0) pre-round + transpose the 4 big weights (one merged launch)
    wtrans4<<<dim3(32, 32, 4), dim3(32, 8)>>>(Wr, Wk, Wv, Wo, wt0, wt1, wt2, wt3);

    // 1) big projections r/k/v merged (mix fused; B via cp.async + paired ldmatrix)
    rkv3<<<dim3(8, 128, 3), 256, SMTCP>>>(x, x_r, x_k, x_v, wt0, wt1, wt2, rB, kB, vB);

    // 2) lora stage 1 merged (tanh fused)
    lora3<<<dim3(1, 128, 3), 256, SM64>>>(x, x_w, x_a, x_g, w1, a1, g1, hw, ha, hg);

    // 3) decay + in-context lr
    wa_kernel<<<(BT * HH) / 256, 256>>>(hw, ha, w2, a2, w0, a0, wd, ab);

    // 4) gate stage 2 (sigmoid fused)
    mma_gemm<128, EPI_SIG, false, false, false><<<dim3(8, 128), 256, SM128>>>(
        hg, nullptr, g2, gate, BT, CC, DLOW);

    // 5) kk normalize + kv  (kk overwrites k in-place)
    kv_kernel<<<(BT * HH) / 8, 256>>>(kB, vB, k_k, ab, kB, kvB);

    // 6) WKV recurrence (wkv overwrites kv in-place)
    scan_kernel<<<8 * HH, 64>>>(kvB, wd, kvB);

    // 7) bonus + GroupNorm + gate (xng overwrites gate in-place, tf32-rounded)
    epi_kernel<<<(BT * HH) / 8, 256>>>(kvB, rB, kB, vB, r_k, gate, lnw, lnb, gate);

    // 8) output projection (A and B both via cp.async + ldmatrix)
    mma_gemm<128, EPI_NONE, false, true, true><<<dim3(8, 128), 256, SMTCP>>>(
        gate, nullptr, wt3, out, BT, CC, CC);
}